// round 14
// baseline (speedup 1.0000x reference)
#include <cuda_runtime.h>
#include <cuda_bf16.h>
#include <math.h>
#include <stdint.h>

typedef __nv_bfloat16 bf16;

#define BSZ 64
#define NN  256
#define CC  512
#define NC  (NN*CC)     // 131072
#define NNN (NN*NN)     // 65536
#define WSZ (CC*CC)     // 262144
#define WFRAG_BYTES (1<<20)
#define BFRAG_BATCH (512<<10)   // 512KB: frag image per batch for K=256,N=512

// fp32 scratch
__device__ float g_S [BSZ*NNN];
__device__ float g_b5[BSZ*NC];
__device__ float g_b6[BSZ*NC];
__device__ float g_Mp[4*WSZ];
// bf16 hi/lo pairs
__device__ __align__(256) bf16 g_fh[BSZ*NC],   g_fl[BSZ*NC];
__device__ __align__(256) bf16 g_b2h[BSZ*NC],  g_b2l[BSZ*NC];
__device__ __align__(256) bf16 g_Sh[BSZ*NNN],  g_Sl[BSZ*NNN];
// fragment-ordered operands
__device__ __align__(256) char g_wfrag[10*WFRAG_BYTES];  // weights + M (B-frag, K=512)
__device__ __align__(256) char g_afF  [32u<<20];         // f     A-frag (K=512)
__device__ __align__(256) char g_afAJ [16u<<20];         // adj   A-frag (K=256)
__device__ __align__(256) char g_afAJT[16u<<20];         // adj^T A-frag (K=256)
__device__ __align__(256) char g_b3f[1u<<25];            // b3 B-frag (K=256,N=512) batched
__device__ __align__(256) char g_b4f[1u<<25];
__device__ __align__(256) char g_b1f[1u<<25];
__device__ __align__(256) char g_c5f[1u<<25];

#define STG        32768
#define SMEM_TOTAL (2*STG)

__device__ __forceinline__ uint32_t smem_u32(const void* p) {
    uint32_t a;
    asm("{ .reg .u64 t; cvta.to.shared.u64 t, %1; cvt.u32.u64 %0, t; }" : "=r"(a) : "l"(p));
    return a;
}
__device__ __forceinline__ uint32_t off_rk(uint32_t r, uint32_t cb) {
    return r * 64u + ((((cb >> 4) ^ ((r >> 1) & 3u)) & 3u) << 4) + (cb & 15u);
}
__device__ __forceinline__ uint32_t off_kn(uint32_t k, uint32_t cb) {
    uint32_t ch = (cb >> 4) ^ (k & 7u);
    return k * 256u + (ch << 4) + (cb & 15u);
}
__device__ __forceinline__ void ldsm4(uint32_t& r0, uint32_t& r1, uint32_t& r2, uint32_t& r3, uint32_t a) {
    asm volatile("ldmatrix.sync.aligned.m8n8.x4.shared.b16 {%0,%1,%2,%3}, [%4];"
                 : "=r"(r0), "=r"(r1), "=r"(r2), "=r"(r3) : "r"(a));
}
__device__ __forceinline__ void ldsm4t(uint32_t& r0, uint32_t& r1, uint32_t& r2, uint32_t& r3, uint32_t a) {
    asm volatile("ldmatrix.sync.aligned.m8n8.x4.trans.shared.b16 {%0,%1,%2,%3}, [%4];"
                 : "=r"(r0), "=r"(r1), "=r"(r2), "=r"(r3) : "r"(a));
}
__device__ __forceinline__ void mma16816(float* c, const uint32_t* a, const uint32_t* b) {
    asm volatile(
        "mma.sync.aligned.m16n8k16.row.col.f32.bf16.bf16.f32 "
        "{%0,%1,%2,%3}, {%4,%5,%6,%7}, {%8,%9}, {%0,%1,%2,%3};"
        : "+f"(c[0]), "+f"(c[1]), "+f"(c[2]), "+f"(c[3])
        : "r"(a[0]), "r"(a[1]), "r"(a[2]), "r"(a[3]), "r"(b[0]), "r"(b[1]));
}
__device__ __forceinline__ void cvt_store8(const float4 v0, const float4 v1,
                                           char* ph, char* pl) {
    float v[8] = {v0.x, v0.y, v0.z, v0.w, v1.x, v1.y, v1.z, v1.w};
    unsigned short hs[8], ls[8];
    #pragma unroll
    for (int e = 0; e < 8; e++) {
        __nv_bfloat16 hb = __float2bfloat16_rn(v[e]);
        float lf = v[e] - __bfloat162float(hb);
        __nv_bfloat16 lb = __float2bfloat16_rn(lf);
        hs[e] = *(unsigned short*)&hb;
        ls[e] = *(unsigned short*)&lb;
    }
    *(uint4*)ph = *(uint4*)hs;
    *(uint4*)pl = *(uint4*)ls;
}

// Stage one 128x32 tile into hi/lo smem.
template<int T, int P>
__device__ __forceinline__ void stage_tile(const void* __restrict__ A,
                                           const void* __restrict__ A2,
                                           int ld, int k0, int r0,
                                           char* sh, char* sl, int tid) {
    #pragma unroll
    for (int it = 0; it < 2; it++) {
        int idx = it * 256 + tid;
        int r, cb8;
        if (T == 0) { r = idx >> 2; cb8 = (idx & 3) * 8; }
        else        { r = idx >> 4; cb8 = (idx & 15) * 8; }
        long o = (T == 0) ? ((long)(r0 + r) * ld + k0 + cb8)
                          : ((long)(k0 + r) * ld + r0 + cb8);
        uint32_t off = (T == 0) ? off_rk((uint32_t)r, (uint32_t)cb8 * 2)
                                : off_kn((uint32_t)r, (uint32_t)cb8 * 2);
        if (P) {
            *(uint4*)(sh + off) = *(const uint4*)((const bf16*)A  + o);
            *(uint4*)(sl + off) = *(const uint4*)((const bf16*)A2 + o);
        } else {
            float4 a = *(const float4*)((const float*)A + o);
            float4 b = *(const float4*)((const float*)A + o + 4);
            if (A2) {
                float4 a2 = *(const float4*)((const float*)A2 + o);
                float4 b2 = *(const float4*)((const float*)A2 + o + 4);
                a.x += a2.x; a.y += a2.y; a.z += a2.z; a.w += a2.w;
                b.x += b2.x; b.y += b2.y; b.z += b2.z; b.w += b2.w;
            }
            cvt_store8(a, b, sh + off, sl + off);
        }
    }
}

// ---------------------------------------------------------------------------
// GEMM body.
//   BF=1: B is a fragment-ordered image (batched via byte stride sB).
//   AF=1: A is a fragment-ordered image.
//   EPI: 0 store | 1 relu | 3 relu + Add1 + Add2.
//   OP:  0 fp32 out | 1 bf16 pair out | 2 B-fragment image out (K=256,N=512).
// ---------------------------------------------------------------------------
template<int TA, int TB, int PA, int PB, int EPI, int OP, int BF, int AF>
__device__ __forceinline__ void gemm_body(
    const void* __restrict__ A, const void* __restrict__ A2,
    const void* __restrict__ B, const void* __restrict__ B2,
    void* __restrict__ C0, void* __restrict__ C1,
    const float* __restrict__ Add1, const float* __restrict__ Add2,
    long sA, int lda, long sB, int ldb, long sC, int ldc, int K,
    char* smem, int nx)
{
    const int tid = threadIdx.x, lane = tid & 31, wid = tid >> 5;
    const int b  = blockIdx.z;
    const int my = blockIdx.y;
    const int m0 = my * 128;
    const int n0 = nx * 128;
    const int nch = K >> 5;

    const void* Ab  = AF ? A
                         : (PA ? (const void*)((const bf16*)A  + (long)b * sA)
                               : (const void*)((const float*)A + (long)b * sA));
    const void* Ab2 = (!AF && PA) ? (const void*)((const bf16*)A2 + (long)b * sA)
                    : ((!AF && A2) ? (const void*)((const float*)A2 + (long)b * sA) : nullptr);
    const void* Bb  = BF ? (const void*)((const char*)B + (long)b * sB)
                         : (PB ? (const void*)((const bf16*)B  + (long)b * sB)
                               : (const void*)((const float*)B + (long)b * sB));
    const void* Bb2 = (!BF && PB) ? (const void*)((const bf16*)B2 + (long)b * sB) : nullptr;

    const int am = (wid & 3) * 32;
    const int bn = (wid >> 2) * 64;
    const int bng = wid >> 2;
    const int amg = wid & 3;
    const bool USE_SMEM = (!AF) || (!BF);

    float acc[2][8][4];
    #pragma unroll
    for (int i = 0; i < 2; i++)
        #pragma unroll
        for (int j = 0; j < 8; j++)
            #pragma unroll
            for (int e = 0; e < 4; e++) acc[i][j][e] = 0.f;

    if (!AF) stage_tile<TA,PA>(Ab, Ab2, lda, 0, m0, smem, smem + 8192, tid);
    if (!BF) stage_tile<TB,PB>(Bb, Bb2, ldb, 0, n0, smem + 16384, smem + 24576, tid);
    if (USE_SMEM) __syncthreads();

    for (int ch = 0; ch < nch; ch++) {
        const int d = ch & 1;
        char* cur = smem + d * STG;
        if (ch + 1 < nch) {
            char* nxt = smem + (d ^ 1) * STG;
            if (!AF) stage_tile<TA,PA>(Ab, Ab2, lda, (ch + 1) << 5, m0, nxt, nxt + 8192, tid);
            if (!BF) stage_tile<TB,PB>(Bb, Bb2, ldb, (ch + 1) << 5, n0, nxt + 16384, nxt + 24576, tid);
        }
        const uint32_t uAh = smem_u32(cur);
        const uint32_t uAl = uAh + 8192;
        const uint32_t uBh = uAh + 16384;
        const uint32_t uBl = uAh + 24576;

        #pragma unroll
        for (int ks = 0; ks < 2; ks++) {
            uint32_t Ahf[2][4], Alf[2][4];
            if (AF) {
                const char* Af = (const char*)Ab;
                long base = ((((long)b * 2 + my) * nch + ch) * 2 + ks) * 4 + amg;
                #pragma unroll
                for (int mt = 0; mt < 2; mt++) {
                    uint4 v = *(const uint4*)(Af + ((base * 2 + mt) * 2 + 0) * 512 + lane * 16);
                    Ahf[mt][0] = v.x; Ahf[mt][1] = v.y; Ahf[mt][2] = v.z; Ahf[mt][3] = v.w;
                    uint4 u = *(const uint4*)(Af + ((base * 2 + mt) * 2 + 1) * 512 + lane * 16);
                    Alf[mt][0] = u.x; Alf[mt][1] = u.y; Alf[mt][2] = u.z; Alf[mt][3] = u.w;
                }
            } else {
                #pragma unroll
                for (int mt = 0; mt < 2; mt++) {
                    uint32_t off;
                    if (!TA) {
                        uint32_t row = (uint32_t)(am + mt * 16 + (lane & 15));
                        uint32_t cb  = (uint32_t)(ks * 32 + ((lane >> 4) << 4));
                        off = off_rk(row, cb);
                    } else {
                        uint32_t grp = lane >> 3, t8 = lane & 7;
                        uint32_t k   = (uint32_t)(ks * 16) + ((grp >> 1) << 3) + t8;
                        uint32_t cb  = (uint32_t)(am + mt * 16 + ((grp & 1) << 3)) * 2;
                        off = off_kn(k, cb);
                    }
                    if (!TA) {
                        ldsm4(Ahf[mt][0], Ahf[mt][1], Ahf[mt][2], Ahf[mt][3], uAh + off);
                        ldsm4(Alf[mt][0], Alf[mt][1], Alf[mt][2], Alf[mt][3], uAl + off);
                    } else {
                        ldsm4t(Ahf[mt][0], Ahf[mt][1], Ahf[mt][2], Ahf[mt][3], uAh + off);
                        ldsm4t(Alf[mt][0], Alf[mt][1], Alf[mt][2], Alf[mt][3], uAl + off);
                    }
                }
            }
            uint32_t Bhf[8][2], Blf[8][2];
            if (BF) {
                long blk = ((((long)nx * nch + ch) * 2 + ks) * 2) * 2 + bng;
                const char* ph = (const char*)Bb + blk * 2048;
                const char* pl = ph + 4096;
                #pragma unroll
                for (int j = 0; j < 4; j++) {
                    uint4 v = *(const uint4*)(ph + (j * 32 + lane) * 16);
                    Bhf[2*j][0] = v.x; Bhf[2*j][1] = v.y;
                    Bhf[2*j+1][0] = v.z; Bhf[2*j+1][1] = v.w;
                }
                #pragma unroll
                for (int j = 0; j < 4; j++) {
                    uint4 v = *(const uint4*)(pl + (j * 32 + lane) * 16);
                    Blf[2*j][0] = v.x; Blf[2*j][1] = v.y;
                    Blf[2*j+1][0] = v.z; Blf[2*j+1][1] = v.w;
                }
            } else {
                #pragma unroll
                for (int p = 0; p < 4; p++) {
                    uint32_t off;
                    if (!TB) {
                        uint32_t row = (uint32_t)(bn + p * 16 + (lane & 15));
                        uint32_t cb  = (uint32_t)(ks * 32 + ((lane >> 4) << 4));
                        off = off_rk(row, cb);
                    } else {
                        uint32_t grp = lane >> 3, t8 = lane & 7;
                        uint32_t k   = (uint32_t)(ks * 16) + ((grp >> 1) << 3) + t8;
                        uint32_t cb  = (uint32_t)(bn + p * 16 + ((grp & 1) << 3)) * 2;
                        off = off_kn(k, cb);
                    }
                    uint32_t r0, r1, r2, r3;
                    if (!TB) ldsm4 (r0, r1, r2, r3, uBh + off);
                    else     ldsm4t(r0, r1, r2, r3, uBh + off);
                    Bhf[2*p][0] = r0; Bhf[2*p][1] = r2; Bhf[2*p+1][0] = r1; Bhf[2*p+1][1] = r3;
                    if (!TB) ldsm4 (r0, r1, r2, r3, uBl + off);
                    else     ldsm4t(r0, r1, r2, r3, uBl + off);
                    Blf[2*p][0] = r0; Blf[2*p][1] = r2; Blf[2*p+1][0] = r1; Blf[2*p+1][1] = r3;
                }
            }
            #pragma unroll
            for (int mt = 0; mt < 2; mt++)
                #pragma unroll
                for (int nt = 0; nt < 8; nt++) {
                    mma16816(acc[mt][nt], Ahf[mt], Bhf[nt]);
                    mma16816(acc[mt][nt], Ahf[mt], Blf[nt]);
                    mma16816(acc[mt][nt], Alf[mt], Bhf[nt]);
                }
        }
        if (USE_SMEM) __syncthreads();
    }

    if (OP == 2) {
        // Write output tile as a B-fragment image (k = out-row token, n = out-col).
        // 1) bounce tile into smem in off_kn layout: 4 chunks of (32k x 128n), hi+lo.
        #pragma unroll
        for (int mt = 0; mt < 2; mt++) {
            #pragma unroll
            for (int half = 0; half < 2; half++) {
                int r = am + mt * 16 + (lane >> 2) + half * 8;    // 0..127 token
                char* sh = smem + (r >> 5) * 16384;
                uint32_t kk = (uint32_t)(r & 31);
                #pragma unroll
                for (int nt = 0; nt < 8; nt++) {
                    float x = acc[mt][nt][half * 2 + 0];
                    float y = acc[mt][nt][half * 2 + 1];
                    if (EPI >= 1) { x = fmaxf(x, 0.f); y = fmaxf(y, 0.f); }
                    uint32_t c = (uint32_t)(bn + nt * 8 + (lane & 3) * 2);
                    __nv_bfloat162 hv, lv;
                    hv.x = __float2bfloat16_rn(x);
                    lv.x = __float2bfloat16_rn(x - __bfloat162float(hv.x));
                    hv.y = __float2bfloat16_rn(y);
                    lv.y = __float2bfloat16_rn(y - __bfloat162float(hv.y));
                    uint32_t off = off_kn(kk, c * 2);
                    *(__nv_bfloat162*)(sh + off)        = hv;
                    *(__nv_bfloat162*)(sh + 8192 + off) = lv;
                }
            }
        }
        __syncthreads();
        // 2) replay ldsm4t fragment reads and STG raw frags.
        {
            const int cc = wid >> 1, ksx = wid & 1;
            const uint32_t grp = lane >> 3, t8 = lane & 7;
            const int nx_c = n0 >> 7;
            const int ch_c = (m0 >> 5) + cc;
            char* imgbase = (char*)C0 + (long)b * BFRAG_BATCH;
            #pragma unroll
            for (int part = 0; part < 2; part++) {
                const uint32_t sb = smem_u32(smem) + (uint32_t)cc * 16384 + (uint32_t)part * 8192;
                #pragma unroll
                for (int bg = 0; bg < 2; bg++) {
                    uint32_t regs[16];
                    #pragma unroll
                    for (int p = 0; p < 4; p++) {
                        uint32_t k  = (uint32_t)(ksx * 16) + ((grp >> 1) << 3) + t8;
                        uint32_t cb = (uint32_t)(bg * 64 + p * 16 + ((grp & 1) << 3)) * 2;
                        uint32_t r0, r1, r2, r3;
                        ldsm4t(r0, r1, r2, r3, sb + off_kn(k, cb));
                        regs[4*p+0] = r0; regs[4*p+1] = r2; regs[4*p+2] = r1; regs[4*p+3] = r3;
                    }
                    long blk = ((((long)nx_c * 8 + ch_c) * 2 + ksx) * 2 + part) * 2 + bg;
                    char* d = imgbase + blk * 2048;
                    #pragma unroll
                    for (int j = 0; j < 4; j++)
                        *(uint4*)(d + (j * 32 + lane) * 16) =
                            make_uint4(regs[4*j], regs[4*j+1], regs[4*j+2], regs[4*j+3]);
                }
            }
        }
        return;
    }

    #pragma unroll
    for (int mt = 0; mt < 2; mt++) {
        #pragma unroll
        for (int half = 0; half < 2; half++) {
            int row = m0 + am + mt * 16 + (lane >> 2) + half * 8;
            long base = (long)b * sC + (long)row * ldc + n0 + bn + (lane & 3) * 2;
            #pragma unroll
            for (int nt = 0; nt < 8; nt++) {
                float x = acc[mt][nt][half * 2 + 0];
                float y = acc[mt][nt][half * 2 + 1];
                if (EPI >= 1) { x = fmaxf(x, 0.f); y = fmaxf(y, 0.f); }
                if (EPI == 3) {
                    float2 o1 = *(const float2*)(Add1 + base + nt * 8);
                    float2 o2 = *(const float2*)(Add2 + base + nt * 8);
                    x += (o1.x + o2.x); y += (o1.y + o2.y);
                }
                if (OP == 1) {
                    __nv_bfloat162 hv, lv;
                    hv.x = __float2bfloat16_rn(x);
                    lv.x = __float2bfloat16_rn(x - __bfloat162float(hv.x));
                    hv.y = __float2bfloat16_rn(y);
                    lv.y = __float2bfloat16_rn(y - __bfloat162float(hv.y));
                    *(__nv_bfloat162*)((bf16*)C0 + base + nt * 8) = hv;
                    *(__nv_bfloat162*)((bf16*)C1 + base + nt * 8) = lv;
                } else {
                    float2 v; v.x = x; v.y = y;
                    *(float2*)((float*)C0 + base + nt * 8) = v;
                }
            }
        }
    }
}

// ---------------------------------------------------------------------------
template<int PARTS,
         int TA0,int TB0,int PA0,int PB0,int EPI0,int OP0,int BF0,int AF0,
         int TA1,int TB1,int PA1,int PB1,int EPI1,int OP1,int BF1,int AF1,
         int TA2,int TB2,int PA2,int PB2,int EPI2,int OP2,int BF2,int AF2,
         int TA3,int TB3,int PA3,int PB3,int EPI3,int OP3,int BF3,int AF3>
__global__ __launch_bounds__(256)
void tc_multi(
    const void* A0, const void* A20, const void* B0, const void* B20, void* C00, void* C01,
    const void* A1, const void* A21, const void* B1, const void* B21, void* C10, void* C11,
    const void* A2, const void* A22, const void* B2, const void* B22, void* C20, void* C21,
    const void* A3, const void* A23, const void* B3, const void* B23, void* C30, void* C31,
    const float* Add1, const float* Add2,
    long sA, int lda, long sB, int ldb, long sC, int ldc, int K)
{
    extern __shared__ char smem[];
    const int p  = blockIdx.x >> 2;
    const int nx = blockIdx.x & 3;
    if (PARTS >= 4 && p == 3)
        gemm_body<TA3,TB3,PA3,PB3,EPI3,OP3,BF3,AF3>(A3, A23, B3, B23, C30, C31, Add1, Add2,
                                                    sA, lda, sB, ldb, sC, ldc, K, smem, nx);
    else if (PARTS >= 3 && p == 2)
        gemm_body<TA2,TB2,PA2,PB2,EPI2,OP2,BF2,AF2>(A2, A22, B2, B22, C20, C21, Add1, Add2,
                                                    sA, lda, sB, ldb, sC, ldc, K, smem, nx);
    else if (PARTS >= 2 && p == 1)
        gemm_body<TA1,TB1,PA1,PB1,EPI1,OP1,BF1,AF1>(A1, A21, B1, B21, C10, C11, Add1, Add2,
                                                    sA, lda, sB, ldb, sC, ldc, K, smem, nx);
    else
        gemm_body<TA0,TB0,PA0,PB0,EPI0,OP0,BF0,AF0>(A0, A20, B0, B20, C00, C01, Add1, Add2,
                                                    sA, lda, sB, ldb, sC, ldc, K, smem, nx);
}

// ---------------------------------------------------------------------------
__global__ __launch_bounds__(256)
void softmax_kernel(const float* __restrict__ S, bf16* __restrict__ Sh, bf16* __restrict__ Sl)
{
    __shared__ float sm[8];
    const long row = blockIdx.x;
    const float* p = S + row * (long)NN;
    const int t = threadIdx.x;

    float v = p[t];
    float m = v;
    #pragma unroll
    for (int o = 16; o > 0; o >>= 1) m = fmaxf(m, __shfl_xor_sync(0xffffffffu, m, o));
    if ((t & 31) == 0) sm[t >> 5] = m;
    __syncthreads();
    m = sm[0];
    #pragma unroll
    for (int i = 1; i < 8; i++) m = fmaxf(m, sm[i]);

    float e = expf(v - m);
    float s = e;
    #pragma unroll
    for (int o = 16; o > 0; o >>= 1) s += __shfl_xor_sync(0xffffffffu, s, o);
    __syncthreads();
    if ((t & 31) == 0) sm[t >> 5] = s;
    __syncthreads();
    s = 0.f;
    #pragma unroll
    for (int i = 0; i < 8; i++) s += sm[i];

    float r = e / s;
    bf16 hb = __float2bfloat16_rn(r);
    Sh[row * (long)NN + t] = hb;
    Sl[row * (long)NN + t] = __float2bfloat16_rn(r - __bfloat162float(hb));
}

// ---------------------------------------------------------------------------
__global__ __launch_bounds__(256)
void pack8(const float* __restrict__ src, bf16* __restrict__ dh, bf16* __restrict__ dl, long n8)
{
    long i = (long)blockIdx.x * 256 + threadIdx.x;
    if (i >= n8) return;
    long o = i * 8;
    float4 a = *(const float4*)(src + o);
    float4 b = *(const float4*)(src + o + 4);
    cvt_store8(a, b, (char*)(dh + o), (char*)(dl + o));
}

__global__ __launch_bounds__(256)
void sum4_f32(float* __restrict__ mp)
{
    long i = (long)blockIdx.x * 256 + threadIdx.x;
    long o = i * 8;
    float4 a = *(const float4*)(mp + o);
    float4 b = *(const float4*)(mp + o + 4);
    #pragma unroll
    for (int z = 1; z < 4; z++) {
        float4 a2 = *(const float4*)(mp + (long)z * WSZ + o);
        float4 b2 = *(const float4*)(mp + (long)z * WSZ + o + 4);
        a.x += a2.x; a.y += a2.y; a.z += a2.z; a.w += a2.w;
        b.x += b2.x; b.y += b2.y; b.z += b2.z; b.w += b2.w;
    }
    *(float4*)(mp + o)     = a;
    *(float4*)(mp + o + 4) = b;
}

// Repack 512x512 fp32 weight into B-fragment order (K=512).
__global__ __launch_bounds__(256)
void repack_w(const float* s0, const float* s1, const float* s2, const float* s3,
              const float* s4, const float* s5, const float* s6, const float* s7,
              const float* s8, const float* s9, char* __restrict__ dst)
{
    __shared__ char sm[16384];
    const int z = blockIdx.z;
    const float* s;
    switch (z) {
        case 0: s = s0; break; case 1: s = s1; break; case 2: s = s2; break;
        case 3: s = s3; break; case 4: s = s4; break; case 5: s = s5; break;
        case 6: s = s6; break; case 7: s = s7; break; case 8: s = s8; break;
        default: s = s9; break;
    }
    const int nx = blockIdx.x >> 4, ch = blockIdx.x & 15;
    const int tid = threadIdx.x, lane = tid & 31, w = tid >> 5;

    stage_tile<1,0>(s, nullptr, CC, ch * 32, nx * 128, sm, sm + 8192, tid);
    __syncthreads();

    const int part = w & 1, bng = (w >> 1) & 1, ks = w >> 2;
    const uint32_t base = smem_u32(sm) + (uint32_t)part * 8192;
    const uint32_t grp = lane >> 3, t8 = lane & 7;
    uint32_t regs[16];
    #pragma unroll
    for (int p = 0; p < 4; p++) {
        uint32_t k  = (uint32_t)(ks * 16) + ((grp >> 1) << 3) + t8;
        uint32_t cb = (uint32_t)(bng * 64 + p * 16 + ((grp & 1) << 3)) * 2;
        uint32_t off = off_kn(k, cb);
        uint32_t r0, r1, r2, r3;
        ldsm4t(r0, r1, r2, r3, base + off);
        regs[4*p+0] = r0; regs[4*p+1] = r2; regs[4*p+2] = r1; regs[4*p+3] = r3;
    }
    long blk = ((((long)nx * 16 + ch) * 2 + ks) * 2 + part) * 2 + bng;
    char* d = dst + (long)z * WFRAG_BYTES + blk * 2048;
    #pragma unroll
    for (int j = 0; j < 4; j++)
        *(uint4*)(d + (j * 32 + lane) * 16) =
            make_uint4(regs[4*j], regs[4*j+1], regs[4*j+2], regs[4*j+3]);
}

// Repack fp32 batched matrix into A-fragment order.
template<int T>
__global__ __launch_bounds__(256)
void repack_afrag(const float* __restrict__ src, long sSrc, int ld, int nch,
                  char* __restrict__ dst)
{
    __shared__ char sm[16384];
    const int b = blockIdx.z;
    const int mtile = blockIdx.x / nch;
    const int ch = blockIdx.x - mtile * nch;
    const int tid = threadIdx.x, lane = tid & 31, w = tid >> 5;

    stage_tile<T,0>(src + (long)b * sSrc, nullptr, ld, ch * 32, mtile * 128,
                    sm, sm + 8192, tid);
    __syncthreads();

    const int amg = w & 3, ks = w >> 2;
    long base = ((((long)b * 2 + mtile) * nch + ch) * 2 + ks) * 4 + amg;
    #pragma unroll
    for (int mt = 0; mt < 2; mt++) {
        #pragma unroll
        for (int part = 0; part < 2; part++) {
            const uint32_t sb = smem_u32(sm) + (uint32_t)part * 8192;
            uint32_t r0, r1, r2, r3;
            if (T == 0) {
                uint32_t row = (uint32_t)(amg * 32 + mt * 16 + (lane & 15));
                uint32_t cb  = (uint32_t)(ks * 32 + ((lane >> 4) << 4));
                ldsm4(r0, r1, r2, r3, sb + off_rk(row, cb));
            } else {
                uint32_t grp = lane >> 3, t8 = lane & 7;
                uint32_t k   = (uint32_t)(ks * 16) + ((grp >> 1) << 3) + t8;
                uint32_t cb  = (uint32_t)(amg * 32 + mt * 16 + ((grp & 1) << 3)) * 2;
                ldsm4t(r0, r1, r2, r3, sb + off_kn(k, cb));
            }
            char* d = dst + ((base * 2 + mt) * 2 + part) * 512 + lane * 16;
            *(uint4*)d = make_uint4(r0, r1, r2, r3);
        }
    }
}

// Instantiations
#define Z8 0,0,0,0,0,0,0,0
#define KM  tc_multi<1, 1,1,0,0,0,0,0,0, Z8, Z8, Z8>
#define KW4 tc_multi<4, 0,1,1,1,0,2,1,1, 0,1,1,1,0,2,1,1, 0,1,1,1,0,2,1,1, 0,1,1,1,0,1,1,1>
#define KSG tc_multi<1, 0,0,1,1,0,0,0,0, Z8, Z8, Z8>
#define KG3 tc_multi<3, 0,1,1,1,1,0,1,1, 0,1,1,1,1,1,1,0, 1,1,1,1,1,0,1,1, Z8>
#define KW3 tc_multi<3, 0,1,0,1,0,2,1,0, 0,1,0,1,0,2,1,0, 0,1,1,1,0,2,1,0, Z8>
#define KG2 tc_multi<2, 0,1,1,1,1,0,1,1, 1,1,1,1,1,0,1,1, Z8, Z8>
#define KFI tc_multi<1, 0,1,1,1,3,0,1,0, Z8, Z8, Z8>

// ---------------------------------------------------------------------------
extern "C" void kernel_launch(void* const* d_in, const int* in_sizes, int n_in,
                              void* d_out, int out_size)
{
    const float* f     = (const float*)d_in[0];
    const float* adj   = (const float*)d_in[2];
    const float* Wse1  = (const float*)d_in[3];
    const float* Wse2  = (const float*)d_in[4];
    const float* Wst1  = (const float*)d_in[5];
    const float* Wst2  = (const float*)d_in[6];
    const float* Wst3  = (const float*)d_in[7];
    const float* Wst1b = (const float*)d_in[8];
    const float* Wst2b = (const float*)d_in[9];
    const float* Wst3b = (const float*)d_in[10];
    const float* Wsim1 = (const float*)d_in[11];
    const float* Wsim2 = (const float*)d_in[12];
    const float* Wsim3 = (const float*)d_in[13];
    float* out = (float*)d_out;

    float *S, *b5, *b6, *Mp;
    bf16 *fh, *fl, *b2h, *b2l, *Sh, *Sl;
    char *wf, *afF, *afAJ, *afAJT, *b3f, *b4f, *b1f, *c5f;
    cudaGetSymbolAddress((void**)&S,  g_S);   cudaGetSymbolAddress((void**)&b5, g_b5);
    cudaGetSymbolAddress((void**)&b6, g_b6);  cudaGetSymbolAddress((void**)&Mp, g_Mp);
    cudaGetSymbolAddress((void**)&fh,  g_fh);  cudaGetSymbolAddress((void**)&fl,  g_fl);
    cudaGetSymbolAddress((void**)&b2h, g_b2h); cudaGetSymbolAddress((void**)&b2l, g_b2l);
    cudaGetSymbolAddress((void**)&Sh,  g_Sh);  cudaGetSymbolAddress((void**)&Sl,  g_Sl);
    cudaGetSymbolAddress((void**)&wf,  g_wfrag);
    cudaGetSymbolAddress((void**)&afF,  g_afF);
    cudaGetSymbolAddress((void**)&afAJ, g_afAJ);
    cudaGetSymbolAddress((void**)&afAJT,g_afAJT);
    cudaGetSymbolAddress((void**)&b3f, g_b3f);
    cudaGetSymbolAddress((void**)&b4f, g_b4f);
    cudaGetSymbolAddress((void**)&b1f, g_b1f);
    cudaGetSymbolAddress((void**)&c5f, g_c5f);

    cudaFuncSetAttribute(KM,  cudaFuncAttributeMaxDynamicSharedMemorySize, SMEM_TOTAL);
    cudaFuncSetAttribute(KW4, cudaFuncAttributeMaxDynamicSharedMemorySize, SMEM_TOTAL);
    cudaFuncSetAttribute(KSG, cudaFuncAttributeMaxDynamicSharedMemorySize, SMEM_TOTAL);
    cudaFuncSetAttribute(KG3, cudaFuncAttributeMaxDynamicSharedMemorySize, SMEM_TOTAL);
    cudaFuncSetAttribute(KW3, cudaFuncAttributeMaxDynamicSharedMemorySize, SMEM_TOTAL);
    cudaFuncSetAttribute(KG2, cudaFuncAttributeMaxDynamicSharedMemorySize, SMEM_TOTAL);
    cudaFuncSetAttribute(KFI, cudaFuncAttributeMaxDynamicSharedMemorySize, SMEM_TOTAL);

    const dim3 blk(256);
    const int SM = SMEM_TOTAL;
    const void* Z = nullptr;
    void* ZC = nullptr;
    #define P8Z  Z, Z, Z, Z, ZC, ZC
    #define WF(i) ((const void*)(wf + (long)(i)*WFRAG_BYTES))
    const long FB = (long)BFRAG_BATCH;

    // ---- packs / repacks ----
    pack8<<<(int)((long)BSZ*NC/8/256), blk>>>(f, fh, fl, (long)BSZ*NC/8);
    repack_afrag<0><<<dim3(32,1,BSZ), blk>>>(f,   NC,  CC, 16, afF);
    repack_afrag<0><<<dim3(16,1,BSZ), blk>>>(adj, NNN, NN, 8,  afAJ);
    repack_afrag<1><<<dim3(16,1,BSZ), blk>>>(adj, NNN, NN, 8,  afAJT);

    // ---- M = Wse1^T @ Wse2 (split-K x4), sum, repack weights ----
    KM<<<dim3(4,4,4), blk, SM>>>(Wse1, Z, Wse2, Z, Mp, ZC,
                                 P8Z, P8Z, P8Z, nullptr, nullptr,
                                 128*CC, CC, 128*CC, CC, WSZ, CC, 128);
    sum4_f32<<<WSZ/8/256, blk>>>(Mp);
    repack_w<<<dim3(64,1,10), blk>>>(Wst1, Wst1b, Wst2, Wst2b, Wst3, Wst3b,
                                     Wsim1, Wsim2, Wsim3, Mp, wf);

    // ---- stage A: b3f=f@Wst1, b4f=f@Wst1b, b1f=f@Wsim1 (frag outs), b2=f@M pair ----
    KW4<<<dim3(16,2,BSZ), blk, SM>>>(
        afF, Z, WF(0), Z, b3f, ZC,
        afF, Z, WF(1), Z, b4f, ZC,
        afF, Z, WF(6), Z, b1f, ZC,
        afF, Z, WF(9), Z, b2h, b2l,
        nullptr, nullptr, NC, CC, 0, CC, NC, CC, CC);

    // ---- S = b2 @ f^T (fp32), then softmax -> pair ----
    KSG<<<dim3(2,2,BSZ), blk, SM>>>(
        b2h, b2l, fh, fl, S, ZC,
        P8Z, P8Z, P8Z, nullptr, nullptr, NC, CC, NC, CC, NNN, NN, CC);
    softmax_kernel<<<BSZ*NN, blk>>>(S, Sh, Sl);

    // ---- stage B: b5=relu(adj@b3), b2=relu(S@b1) pair, b6=relu(adjT@b4) ----
    KG3<<<dim3(12,2,BSZ), blk, SM>>>(
        afAJ, Z,  b3f, Z, b5,  ZC,
        Sh,  Sl,  b1f, Z, b2h, b2l,
        afAJT, Z, b4f, Z, b6,  ZC,
        P8Z, nullptr, nullptr, NNN, NN, FB, CC, NC, CC, NN);

    // ---- stage C: b3f=(b5+b6)@Wst2, b4f=(b5+b6)@Wst2b, b1f=b2@Wsim2 ----
    KW3<<<dim3(12,2,BSZ), blk, SM>>>(
        b5, b6, WF(2), Z, b3f, ZC,
        b5, b6, WF(3), Z, b4f, ZC,
        b2h, b2l, WF(7), Z, b1f, ZC,
        P8Z, nullptr, nullptr, NC, CC, 0, CC, NC, CC, CC);

    // ---- stage D ----
    KG3<<<dim3(12,2,BSZ), blk, SM>>>(
        afAJ, Z,  b3f, Z, b5,  ZC,
        Sh,  Sl,  b1f, Z, b2h, b2l,
        afAJT, Z, b4f, Z, b6,  ZC,
        P8Z, nullptr, nullptr, NNN, NN, FB, CC, NC, CC, NN);

    // ---- stage E: b3f=(b5+b6)@Wst3, b4f=(b5+b6)@Wst3b, c5f=b2@Wsim3 ----
    KW3<<<dim3(12,2,BSZ), blk, SM>>>(
        b5, b6, WF(4), Z, b3f, ZC,
        b5, b6, WF(5), Z, b4f, ZC,
        b2h, b2l, WF(8), Z, c5f, ZC,
        P8Z, nullptr, nullptr, NC, CC, 0, CC, NC, CC, CC);

    // ---- stage F: b5=relu(adj@b3), b6=relu(adjT@b4) ----
    KG2<<<dim3(8,2,BSZ), blk, SM>>>(
        afAJ, Z,  b3f, Z, b5, ZC,
        afAJT, Z, b4f, Z, b6, ZC,
        P8Z, P8Z, nullptr, nullptr, NNN, NN, FB, CC, NC, CC, NN);

    // ---- out = relu(S@c5) + b5 + b6 ----
    KFI<<<dim3(4,2,BSZ), blk, SM>>>(
        Sh, Sl, c5f, Z, out, ZC,
        P8Z, P8Z, P8Z, b5, b6, NNN, NN, FB, CC, NC, CC, NN);
}

// round 15
// speedup vs baseline: 1.2317x; 1.2317x over previous
#include <cuda_runtime.h>
#include <cuda_bf16.h>
#include <math.h>
#include <stdint.h>

typedef __nv_bfloat16 bf16;

#define BSZ 64
#define NN  256
#define CC  512
#define NC  (NN*CC)     // 131072
#define NNN (NN*NN)     // 65536
#define WSZ (CC*CC)     // 262144
#define WFRAG_BYTES (1<<20)

// fp32 scratch
__device__ float g_S [BSZ*NNN];
__device__ float g_b5[BSZ*NC];
__device__ float g_b6[BSZ*NC];
__device__ float g_Mp[4*WSZ];
// bf16 hi/lo pairs
__device__ __align__(256) bf16 g_fh[BSZ*NC],   g_fl[BSZ*NC];
__device__ __align__(256) bf16 g_b1h[BSZ*NC],  g_b1l[BSZ*NC];
__device__ __align__(256) bf16 g_b2h[BSZ*NC],  g_b2l[BSZ*NC];
__device__ __align__(256) bf16 g_b3h[BSZ*NC],  g_b3l[BSZ*NC];
__device__ __align__(256) bf16 g_b4h[BSZ*NC],  g_b4l[BSZ*NC];
__device__ __align__(256) bf16 g_c5h[BSZ*NC],  g_c5l[BSZ*NC];
__device__ __align__(256) bf16 g_Sh[BSZ*NNN],  g_Sl[BSZ*NNN];
// fragment-ordered operands
__device__ __align__(256) char g_wfrag[10*WFRAG_BYTES];  // B-frags: weights + M
__device__ __align__(256) char g_afF  [32u<<20];         // f     A-frag (K=512)
__device__ __align__(256) char g_afAJ [16u<<20];         // adj   A-frag (K=256)
__device__ __align__(256) char g_afAJT[16u<<20];         // adj^T A-frag (K=256)

#define STG        32768
#define SMEM_TOTAL (2*STG)

__device__ __forceinline__ uint32_t smem_u32(const void* p) {
    uint32_t a;
    asm("{ .reg .u64 t; cvta.to.shared.u64 t, %1; cvt.u32.u64 %0, t; }" : "=r"(a) : "l"(p));
    return a;
}
__device__ __forceinline__ uint32_t off_rk(uint32_t r, uint32_t cb) {
    return r * 64u + ((((cb >> 4) ^ ((r >> 1) & 3u)) & 3u) << 4) + (cb & 15u);
}
__device__ __forceinline__ uint32_t off_kn(uint32_t k, uint32_t cb) {
    uint32_t ch = (cb >> 4) ^ (k & 7u);
    return k * 256u + (ch << 4) + (cb & 15u);
}
__device__ __forceinline__ void ldsm4(uint32_t& r0, uint32_t& r1, uint32_t& r2, uint32_t& r3, uint32_t a) {
    asm volatile("ldmatrix.sync.aligned.m8n8.x4.shared.b16 {%0,%1,%2,%3}, [%4];"
                 : "=r"(r0), "=r"(r1), "=r"(r2), "=r"(r3) : "r"(a));
}
__device__ __forceinline__ void ldsm4t(uint32_t& r0, uint32_t& r1, uint32_t& r2, uint32_t& r3, uint32_t a) {
    asm volatile("ldmatrix.sync.aligned.m8n8.x4.trans.shared.b16 {%0,%1,%2,%3}, [%4];"
                 : "=r"(r0), "=r"(r1), "=r"(r2), "=r"(r3) : "r"(a));
}
__device__ __forceinline__ void mma16816(float* c, const uint32_t* a, const uint32_t* b) {
    asm volatile(
        "mma.sync.aligned.m16n8k16.row.col.f32.bf16.bf16.f32 "
        "{%0,%1,%2,%3}, {%4,%5,%6,%7}, {%8,%9}, {%0,%1,%2,%3};"
        : "+f"(c[0]), "+f"(c[1]), "+f"(c[2]), "+f"(c[3])
        : "r"(a[0]), "r"(a[1]), "r"(a[2]), "r"(a[3]), "r"(b[0]), "r"(b[1]));
}
__device__ __forceinline__ void cvt_store8(const float4 v0, const float4 v1,
                                           char* ph, char* pl) {
    float v[8] = {v0.x, v0.y, v0.z, v0.w, v1.x, v1.y, v1.z, v1.w};
    unsigned short hs[8], ls[8];
    #pragma unroll
    for (int e = 0; e < 8; e++) {
        __nv_bfloat16 hb = __float2bfloat16_rn(v[e]);
        float lf = v[e] - __bfloat162float(hb);
        __nv_bfloat16 lb = __float2bfloat16_rn(lf);
        hs[e] = *(unsigned short*)&hb;
        ls[e] = *(unsigned short*)&lb;
    }
    *(uint4*)ph = *(uint4*)hs;
    *(uint4*)pl = *(uint4*)ls;
}

// Stage one 128x32 tile into hi/lo smem.
template<int T, int P>
__device__ __forceinline__ void stage_tile(const void* __restrict__ A,
                                           const void* __restrict__ A2,
                                           int ld, int k0, int r0,
                                           char* sh, char* sl, int tid) {
    #pragma unroll
    for (int it = 0; it < 2; it++) {
        int idx = it * 256 + tid;
        int r, cb8;
        if (T == 0) { r = idx >> 2; cb8 = (idx & 3) * 8; }
        else        { r = idx >> 4; cb8 = (idx & 15) * 8; }
        long o = (T == 0) ? ((long)(r0 + r) * ld + k0 + cb8)
                          : ((long)(k0 + r) * ld + r0 + cb8);
        uint32_t off = (T == 0) ? off_rk((uint32_t)r, (uint32_t)cb8 * 2)
                                : off_kn((uint32_t)r, (uint32_t)cb8 * 2);
        if (P) {
            *(uint4*)(sh + off) = *(const uint4*)((const bf16*)A  + o);
            *(uint4*)(sl + off) = *(const uint4*)((const bf16*)A2 + o);
        } else {
            float4 a = *(const float4*)((const float*)A + o);
            float4 b = *(const float4*)((const float*)A + o + 4);
            if (A2) {
                float4 a2 = *(const float4*)((const float*)A2 + o);
                float4 b2 = *(const float4*)((const float*)A2 + o + 4);
                a.x += a2.x; a.y += a2.y; a.z += a2.z; a.w += a2.w;
                b.x += b2.x; b.y += b2.y; b.z += b2.z; b.w += b2.w;
            }
            cvt_store8(a, b, sh + off, sl + off);
        }
    }
}

// ---------------------------------------------------------------------------
// GEMM body (R13, unchanged).
// ---------------------------------------------------------------------------
template<int TA, int TB, int PA, int PB, int EPI, int OP, int BF, int AF>
__device__ __forceinline__ void gemm_body(
    const void* __restrict__ A, const void* __restrict__ A2,
    const void* __restrict__ B, const void* __restrict__ B2,
    void* __restrict__ C0, void* __restrict__ C1,
    const float* __restrict__ Add1, const float* __restrict__ Add2,
    long sA, int lda, long sB, int ldb, long sC, int ldc, int K,
    char* smem, int nx)
{
    const int tid = threadIdx.x, lane = tid & 31, wid = tid >> 5;
    const int b  = blockIdx.z;
    const int my = blockIdx.y;
    const int m0 = my * 128;
    const int n0 = nx * 128;
    const int nch = K >> 5;

    const void* Ab  = AF ? A
                         : (PA ? (const void*)((const bf16*)A  + (long)b * sA)
                               : (const void*)((const float*)A + (long)b * sA));
    const void* Ab2 = (!AF && PA) ? (const void*)((const bf16*)A2 + (long)b * sA)
                    : ((!AF && A2) ? (const void*)((const float*)A2 + (long)b * sA) : nullptr);
    const void* Bb  = BF ? B
                         : (PB ? (const void*)((const bf16*)B  + (long)b * sB)
                               : (const void*)((const float*)B + (long)b * sB));
    const void* Bb2 = (!BF && PB) ? (const void*)((const bf16*)B2 + (long)b * sB) : nullptr;

    const int am = (wid & 3) * 32;
    const int bn = (wid >> 2) * 64;
    const int bng = wid >> 2;
    const int amg = wid & 3;
    const bool USE_SMEM = (!AF) || (!BF);

    float acc[2][8][4];
    #pragma unroll
    for (int i = 0; i < 2; i++)
        #pragma unroll
        for (int j = 0; j < 8; j++)
            #pragma unroll
            for (int e = 0; e < 4; e++) acc[i][j][e] = 0.f;

    if (!AF) stage_tile<TA,PA>(Ab, Ab2, lda, 0, m0, smem, smem + 8192, tid);
    if (!BF) stage_tile<TB,PB>(Bb, Bb2, ldb, 0, n0, smem + 16384, smem + 24576, tid);
    if (USE_SMEM) __syncthreads();

    for (int ch = 0; ch < nch; ch++) {
        const int d = ch & 1;
        char* cur = smem + d * STG;
        if (ch + 1 < nch) {
            char* nxt = smem + (d ^ 1) * STG;
            if (!AF) stage_tile<TA,PA>(Ab, Ab2, lda, (ch + 1) << 5, m0, nxt, nxt + 8192, tid);
            if (!BF) stage_tile<TB,PB>(Bb, Bb2, ldb, (ch + 1) << 5, n0, nxt + 16384, nxt + 24576, tid);
        }
        const uint32_t uAh = smem_u32(cur);
        const uint32_t uAl = uAh + 8192;
        const uint32_t uBh = uAh + 16384;
        const uint32_t uBl = uAh + 24576;

        #pragma unroll
        for (int ks = 0; ks < 2; ks++) {
            uint32_t Ahf[2][4], Alf[2][4];
            if (AF) {
                const char* Af = (const char*)Ab;
                long base = ((((long)b * 2 + my) * nch + ch) * 2 + ks) * 4 + amg;
                #pragma unroll
                for (int mt = 0; mt < 2; mt++) {
                    uint4 v = *(const uint4*)(Af + ((base * 2 + mt) * 2 + 0) * 512 + lane * 16);
                    Ahf[mt][0] = v.x; Ahf[mt][1] = v.y; Ahf[mt][2] = v.z; Ahf[mt][3] = v.w;
                    uint4 u = *(const uint4*)(Af + ((base * 2 + mt) * 2 + 1) * 512 + lane * 16);
                    Alf[mt][0] = u.x; Alf[mt][1] = u.y; Alf[mt][2] = u.z; Alf[mt][3] = u.w;
                }
            } else {
                #pragma unroll
                for (int mt = 0; mt < 2; mt++) {
                    uint32_t off;
                    if (!TA) {
                        uint32_t row = (uint32_t)(am + mt * 16 + (lane & 15));
                        uint32_t cb  = (uint32_t)(ks * 32 + ((lane >> 4) << 4));
                        off = off_rk(row, cb);
                    } else {
                        uint32_t grp = lane >> 3, t8 = lane & 7;
                        uint32_t k   = (uint32_t)(ks * 16) + ((grp >> 1) << 3) + t8;
                        uint32_t cb  = (uint32_t)(am + mt * 16 + ((grp & 1) << 3)) * 2;
                        off = off_kn(k, cb);
                    }
                    if (!TA) {
                        ldsm4(Ahf[mt][0], Ahf[mt][1], Ahf[mt][2], Ahf[mt][3], uAh + off);
                        ldsm4(Alf[mt][0], Alf[mt][1], Alf[mt][2], Alf[mt][3], uAl + off);
                    } else {
                        ldsm4t(Ahf[mt][0], Ahf[mt][1], Ahf[mt][2], Ahf[mt][3], uAh + off);
                        ldsm4t(Alf[mt][0], Alf[mt][1], Alf[mt][2], Alf[mt][3], uAl + off);
                    }
                }
            }
            uint32_t Bhf[8][2], Blf[8][2];
            if (BF) {
                long blk = ((((long)nx * 16 + ch) * 2 + ks) * 2) * 2 + bng;
                const char* ph = (const char*)Bb + blk * 2048;
                const char* pl = ph + 4096;
                #pragma unroll
                for (int j = 0; j < 4; j++) {
                    uint4 v = *(const uint4*)(ph + (j * 32 + lane) * 16);
                    Bhf[2*j][0] = v.x; Bhf[2*j][1] = v.y;
                    Bhf[2*j+1][0] = v.z; Bhf[2*j+1][1] = v.w;
                }
                #pragma unroll
                for (int j = 0; j < 4; j++) {
                    uint4 v = *(const uint4*)(pl + (j * 32 + lane) * 16);
                    Blf[2*j][0] = v.x; Blf[2*j][1] = v.y;
                    Blf[2*j+1][0] = v.z; Blf[2*j+1][1] = v.w;
                }
            } else {
                #pragma unroll
                for (int p = 0; p < 4; p++) {
                    uint32_t off;
                    if (!TB) {
                        uint32_t row = (uint32_t)(bn + p * 16 + (lane & 15));
                        uint32_t cb  = (uint32_t)(ks * 32 + ((lane >> 4) << 4));
                        off = off_rk(row, cb);
                    } else {
                        uint32_t grp = lane >> 3, t8 = lane & 7;
                        uint32_t k   = (uint32_t)(ks * 16) + ((grp >> 1) << 3) + t8;
                        uint32_t cb  = (uint32_t)(bn + p * 16 + ((grp & 1) << 3)) * 2;
                        off = off_kn(k, cb);
                    }
                    uint32_t r0, r1, r2, r3;
                    if (!TB) ldsm4 (r0, r1, r2, r3, uBh + off);
                    else     ldsm4t(r0, r1, r2, r3, uBh + off);
                    Bhf[2*p][0] = r0; Bhf[2*p][1] = r2; Bhf[2*p+1][0] = r1; Bhf[2*p+1][1] = r3;
                    if (!TB) ldsm4 (r0, r1, r2, r3, uBl + off);
                    else     ldsm4t(r0, r1, r2, r3, uBl + off);
                    Blf[2*p][0] = r0; Blf[2*p][1] = r2; Blf[2*p+1][0] = r1; Blf[2*p+1][1] = r3;
                }
            }
            #pragma unroll
            for (int mt = 0; mt < 2; mt++)
                #pragma unroll
                for (int nt = 0; nt < 8; nt++) {
                    mma16816(acc[mt][nt], Ahf[mt], Bhf[nt]);
                    mma16816(acc[mt][nt], Ahf[mt], Blf[nt]);
                    mma16816(acc[mt][nt], Alf[mt], Bhf[nt]);
                }
        }
        if (USE_SMEM) __syncthreads();
    }

    #pragma unroll
    for (int mt = 0; mt < 2; mt++) {
        #pragma unroll
        for (int half = 0; half < 2; half++) {
            int row = m0 + am + mt * 16 + (lane >> 2) + half * 8;
            long base = (long)b * sC + (long)row * ldc + n0 + bn + (lane & 3) * 2;
            #pragma unroll
            for (int nt = 0; nt < 8; nt++) {
                float x = acc[mt][nt][half * 2 + 0];
                float y = acc[mt][nt][half * 2 + 1];
                if (EPI >= 1) { x = fmaxf(x, 0.f); y = fmaxf(y, 0.f); }
                if (EPI == 3) {
                    float2 o1 = *(const float2*)(Add1 + base + nt * 8);
                    float2 o2 = *(const float2*)(Add2 + base + nt * 8);
                    x += (o1.x + o2.x); y += (o1.y + o2.y);
                }
                if (OP) {
                    __nv_bfloat162 hv, lv;
                    hv.x = __float2bfloat16_rn(x);
                    lv.x = __float2bfloat16_rn(x - __bfloat162float(hv.x));
                    hv.y = __float2bfloat16_rn(y);
                    lv.y = __float2bfloat16_rn(y - __bfloat162float(hv.y));
                    *(__nv_bfloat162*)((bf16*)C0 + base + nt * 8) = hv;
                    *(__nv_bfloat162*)((bf16*)C1 + base + nt * 8) = lv;
                } else {
                    float2 v; v.x = x; v.y = y;
                    *(float2*)((float*)C0 + base + nt * 8) = v;
                }
            }
        }
    }
}

// ---------------------------------------------------------------------------
template<int PARTS,
         int TA0,int TB0,int PA0,int PB0,int EPI0,int OP0,int BF0,int AF0,
         int TA1,int TB1,int PA1,int PB1,int EPI1,int OP1,int BF1,int AF1,
         int TA2,int TB2,int PA2,int PB2,int EPI2,int OP2,int BF2,int AF2,
         int TA3,int TB3,int PA3,int PB3,int EPI3,int OP3,int BF3,int AF3>
__global__ __launch_bounds__(256)
void tc_multi(
    const void* A0, const void* A20, const void* B0, const void* B20, void* C00, void* C01,
    const void* A1, const void* A21, const void* B1, const void* B21, void* C10, void* C11,
    const void* A2, const void* A22, const void* B2, const void* B22, void* C20, void* C21,
    const void* A3, const void* A23, const void* B3, const void* B23, void* C30, void* C31,
    const float* Add1, const float* Add2,
    long sA, int lda, long sB, int ldb, long sC, int ldc, int K)
{
    extern __shared__ char smem[];
    const int p  = blockIdx.x >> 2;
    const int nx = blockIdx.x & 3;
    if (PARTS >= 4 && p == 3)
        gemm_body<TA3,TB3,PA3,PB3,EPI3,OP3,BF3,AF3>(A3, A23, B3, B23, C30, C31, Add1, Add2,
                                                    sA, lda, sB, ldb, sC, ldc, K, smem, nx);
    else if (PARTS >= 3 && p == 2)
        gemm_body<TA2,TB2,PA2,PB2,EPI2,OP2,BF2,AF2>(A2, A22, B2, B22, C20, C21, Add1, Add2,
                                                    sA, lda, sB, ldb, sC, ldc, K, smem, nx);
    else if (PARTS >= 2 && p == 1)
        gemm_body<TA1,TB1,PA1,PB1,EPI1,OP1,BF1,AF1>(A1, A21, B1, B21, C10, C11, Add1, Add2,
                                                    sA, lda, sB, ldb, sC, ldc, K, smem, nx);
    else
        gemm_body<TA0,TB0,PA0,PB0,EPI0,OP0,BF0,AF0>(A0, A20, B0, B20, C00, C01, Add1, Add2,
                                                    sA, lda, sB, ldb, sC, ldc, K, smem, nx);
}

// ---------------------------------------------------------------------------
__global__ __launch_bounds__(256)
void softmax_kernel(const float* __restrict__ S, bf16* __restrict__ Sh, bf16* __restrict__ Sl)
{
    __shared__ float sm[8];
    const long row = blockIdx.x;
    const float* p = S + row * (long)NN;
    const int t = threadIdx.x;

    float v = p[t];
    float m = v;
    #pragma unroll
    for (int o = 16; o > 0; o >>= 1) m = fmaxf(m, __shfl_xor_sync(0xffffffffu, m, o));
    if ((t & 31) == 0) sm[t >> 5] = m;
    __syncthreads();
    m = sm[0];
    #pragma unroll
    for (int i = 1; i < 8; i++) m = fmaxf(m, sm[i]);

    float e = expf(v - m);
    float s = e;
    #pragma unroll
    for (int o = 16; o > 0; o >>= 1) s += __shfl_xor_sync(0xffffffffu, s, o);
    __syncthreads();
    if ((t & 31) == 0) sm[t >> 5] = s;
    __syncthreads();
    s = 0.f;
    #pragma unroll
    for (int i = 0; i < 8; i++) s += sm[i];

    float r = e / s;
    bf16 hb = __float2bfloat16_rn(r);
    Sh[row * (long)NN + t] = hb;
    Sl[row * (long)NN + t] = __float2bfloat16_rn(r - __bfloat162float(hb));
}

// ---------------------------------------------------------------------------
__global__ __launch_bounds__(256)
void pack8(const float* __restrict__ src, bf16* __restrict__ dh, bf16* __restrict__ dl, long n8)
{
    long i = (long)blockIdx.x * 256 + threadIdx.x;
    if (i >= n8) return;
    long o = i * 8;
    float4 a = *(const float4*)(src + o);
    float4 b = *(const float4*)(src + o + 4);
    cvt_store8(a, b, (char*)(dh + o), (char*)(dl + o));
}

// Repack weights into B-fragment order; slot 9 sums the 4 split-K partials of M.
__global__ __launch_bounds__(256)
void repack_w(const float* s0, const float* s1, const float* s2, const float* s3,
              const float* s4, const float* s5, const float* s6, const float* s7,
              const float* s8, const float* mp, char* __restrict__ dst)
{
    __shared__ char sm[16384];
    const int z = blockIdx.z;
    const int nx = blockIdx.x >> 4, ch = blockIdx.x & 15;
    const int tid = threadIdx.x, lane = tid & 31, w = tid >> 5;

    if (z == 9) {
        // stage M tile = sum of 4 partial slices (T=1 layout)
        #pragma unroll
        for (int it = 0; it < 2; it++) {
            int idx = it * 256 + tid;
            int kr = idx >> 4, cb8 = (idx & 15) * 8;
            long o = (long)(ch * 32 + kr) * CC + nx * 128 + cb8;
            float4 a = *(const float4*)(mp + o);
            float4 b = *(const float4*)(mp + o + 4);
            #pragma unroll
            for (int zz = 1; zz < 4; zz++) {
                float4 a2 = *(const float4*)(mp + (long)zz * WSZ + o);
                float4 b2 = *(const float4*)(mp + (long)zz * WSZ + o + 4);
                a.x += a2.x; a.y += a2.y; a.z += a2.z; a.w += a2.w;
                b.x += b2.x; b.y += b2.y; b.z += b2.z; b.w += b2.w;
            }
            uint32_t off = off_kn((uint32_t)kr, (uint32_t)cb8 * 2);
            cvt_store8(a, b, sm + off, sm + 8192 + off);
        }
    } else {
        const float* s;
        switch (z) {
            case 0: s = s0; break; case 1: s = s1; break; case 2: s = s2; break;
            case 3: s = s3; break; case 4: s = s4; break; case 5: s = s5; break;
            case 6: s = s6; break; case 7: s = s7; break; default: s = s8; break;
        }
        stage_tile<1,0>(s, nullptr, CC, ch * 32, nx * 128, sm, sm + 8192, tid);
    }
    __syncthreads();

    const int part = w & 1, bng = (w >> 1) & 1, ks = w >> 2;
    const uint32_t base = smem_u32(sm) + (uint32_t)part * 8192;
    const uint32_t grp = lane >> 3, t8 = lane & 7;
    uint32_t regs[16];
    #pragma unroll
    for (int p = 0; p < 4; p++) {
        uint32_t k  = (uint32_t)(ks * 16) + ((grp >> 1) << 3) + t8;
        uint32_t cb = (uint32_t)(bng * 64 + p * 16 + ((grp & 1) << 3)) * 2;
        uint32_t off = off_kn(k, cb);
        uint32_t r0, r1, r2, r3;
        ldsm4t(r0, r1, r2, r3, base + off);
        regs[4*p+0] = r0; regs[4*p+1] = r2; regs[4*p+2] = r1; regs[4*p+3] = r3;
    }
    long blk = ((((long)nx * 16 + ch) * 2 + ks) * 2 + part) * 2 + bng;
    char* d = dst + (long)z * WFRAG_BYTES + blk * 2048;
    #pragma unroll
    for (int j = 0; j < 4; j++)
        *(uint4*)(d + (j * 32 + lane) * 16) =
            make_uint4(regs[4*j], regs[4*j+1], regs[4*j+2], regs[4*j+3]);
}

// ---------------------------------------------------------------------------
// A-fragment repack body + merged dispatcher (f / adj / adjT in one launch).
// ---------------------------------------------------------------------------
template<int T>
__device__ __forceinline__ void afrag_body(const float* __restrict__ src, long sSrc,
                                           int ld, int nch, char* __restrict__ dst,
                                           int bx)
{
    __shared__ char sm[16384];
    const int b = blockIdx.z;
    const int mtile = bx / nch;
    const int ch = bx - mtile * nch;
    const int tid = threadIdx.x, lane = tid & 31, w = tid >> 5;

    stage_tile<T,0>(src + (long)b * sSrc, nullptr, ld, ch * 32, mtile * 128,
                    sm, sm + 8192, tid);
    __syncthreads();

    const int amg = w & 3, ks = w >> 2;
    long base = ((((long)b * 2 + mtile) * nch + ch) * 2 + ks) * 4 + amg;
    #pragma unroll
    for (int mt = 0; mt < 2; mt++) {
        #pragma unroll
        for (int part = 0; part < 2; part++) {
            const uint32_t sb = smem_u32(sm) + (uint32_t)part * 8192;
            uint32_t r0, r1, r2, r3;
            if (T == 0) {
                uint32_t row = (uint32_t)(amg * 32 + mt * 16 + (lane & 15));
                uint32_t cb  = (uint32_t)(ks * 32 + ((lane >> 4) << 4));
                ldsm4(r0, r1, r2, r3, sb + off_rk(row, cb));
            } else {
                uint32_t grp = lane >> 3, t8 = lane & 7;
                uint32_t k   = (uint32_t)(ks * 16) + ((grp >> 1) << 3) + t8;
                uint32_t cb  = (uint32_t)(amg * 32 + mt * 16 + ((grp & 1) << 3)) * 2;
                ldsm4t(r0, r1, r2, r3, sb + off_kn(k, cb));
            }
            char* d = dst + ((base * 2 + mt) * 2 + part) * 512 + lane * 16;
            *(uint4*)d = make_uint4(r0, r1, r2, r3);
        }
    }
}

__global__ __launch_bounds__(256)
void repack_afrag_all(const float* __restrict__ f, const float* __restrict__ adj,
                      char* dF, char* dAJ, char* dAJT)
{
    const int which = blockIdx.y;
    if (which == 0) {
        afrag_body<0>(f, NC, CC, 16, dF, blockIdx.x);
    } else if (which == 1) {
        if (blockIdx.x >= 16) return;
        afrag_body<0>(adj, NNN, NN, 8, dAJ, blockIdx.x);
    } else {
        if (blockIdx.x >= 16) return;
        afrag_body<1>(adj, NNN, NN, 8, dAJT, blockIdx.x);
    }
}

// Instantiations
#define Z8 0,0,0,0,0,0,0,0
#define KM  tc_multi<1, 1,1,0,0,0,0,0,0, Z8, Z8, Z8>
#define KW4 tc_multi<4, 0,1,1,1,0,1,1,1, 0,1,1,1,0,1,1,1, 0,1,1,1,0,1,1,1, 0,1,1,1,0,1,1,1>
#define KSG tc_multi<1, 0,0,1,1,0,0,0,0, Z8, Z8, Z8>
#define KG3 tc_multi<3, 0,1,1,1,1,0,0,1, 0,1,1,1,1,1,0,0, 1,1,1,1,1,0,0,1, Z8>
#define KW3 tc_multi<3, 0,1,0,1,0,1,1,0, 0,1,0,1,0,1,1,0, 0,1,1,1,0,1,1,0, Z8>
#define KG2 tc_multi<2, 0,1,1,1,1,0,0,1, 1,1,1,1,1,0,0,1, Z8, Z8>
#define KFI tc_multi<1, 0,1,1,1,3,0,0,0, Z8, Z8, Z8>

// ---------------------------------------------------------------------------
extern "C" void kernel_launch(void* const* d_in, const int* in_sizes, int n_in,
                              void* d_out, int out_size)
{
    const float* f     = (const float*)d_in[0];
    const float* adj   = (const float*)d_in[2];
    const float* Wse1  = (const float*)d_in[3];
    const float* Wse2  = (const float*)d_in[4];
    const float* Wst1  = (const float*)d_in[5];
    const float* Wst2  = (const float*)d_in[6];
    const float* Wst3  = (const float*)d_in[7];
    const float* Wst1b = (const float*)d_in[8];
    const float* Wst2b = (const float*)d_in[9];
    const float* Wst3b = (const float*)d_in[10];
    const float* Wsim1 = (const float*)d_in[11];
    const float* Wsim2 = (const float*)d_in[12];
    const float* Wsim3 = (const float*)d_in[13];
    float* out = (float*)d_out;

    float *S, *b5, *b6, *Mp;
    bf16 *fh, *fl;
    bf16 *b1h, *b1l, *b2h, *b2l, *b3h, *b3l, *b4h, *b4l, *c5h, *c5l, *Sh, *Sl;
    char *wf, *afF, *afAJ, *afAJT;
    cudaGetSymbolAddress((void**)&S,  g_S);   cudaGetSymbolAddress((void**)&b5, g_b5);
    cudaGetSymbolAddress((void**)&b6, g_b6);  cudaGetSymbolAddress((void**)&Mp, g_Mp);
    cudaGetSymbolAddress((void**)&fh,  g_fh);  cudaGetSymbolAddress((void**)&fl,  g_fl);
    cudaGetSymbolAddress((void**)&b1h, g_b1h); cudaGetSymbolAddress((void**)&b1l, g_b1l);
    cudaGetSymbolAddress((void**)&b2h, g_b2h); cudaGetSymbolAddress((void**)&b2l, g_b2l);
    cudaGetSymbolAddress((void**)&b3h, g_b3h); cudaGetSymbolAddress((void**)&b3l, g_b3l);
    cudaGetSymbolAddress((void**)&b4h, g_b4h); cudaGetSymbolAddress((void**)&b4l, g_b4l);
    cudaGetSymbolAddress((void**)&c5h, g_c5h); cudaGetSymbolAddress((void**)&c5l, g_c5l);
    cudaGetSymbolAddress((void**)&Sh,  g_Sh);  cudaGetSymbolAddress((void**)&Sl,  g_Sl);
    cudaGetSymbolAddress((void**)&wf,  g_wfrag);
    cudaGetSymbolAddress((void**)&afF,  g_afF);
    cudaGetSymbolAddress((void**)&afAJ, g_afAJ);
    cudaGetSymbolAddress((void**)&afAJT,g_afAJT);

    cudaFuncSetAttribute(KM,  cudaFuncAttributeMaxDynamicSharedMemorySize, SMEM_TOTAL);
    cudaFuncSetAttribute(KW4, cudaFuncAttributeMaxDynamicSharedMemorySize, SMEM_TOTAL);
    cudaFuncSetAttribute(KSG, cudaFuncAttributeMaxDynamicSharedMemorySize, SMEM_TOTAL);
    cudaFuncSetAttribute(KG3, cudaFuncAttributeMaxDynamicSharedMemorySize, SMEM_TOTAL);
    cudaFuncSetAttribute(KW3, cudaFuncAttributeMaxDynamicSharedMemorySize, SMEM_TOTAL);
    cudaFuncSetAttribute(KG2, cudaFuncAttributeMaxDynamicSharedMemorySize, SMEM_TOTAL);
    cudaFuncSetAttribute(KFI, cudaFuncAttributeMaxDynamicSharedMemorySize, SMEM_TOTAL);

    const dim3 blk(256);
    const int SM = SMEM_TOTAL;
    const void* Z = nullptr;
    void* ZC = nullptr;
    #define P8Z  Z, Z, Z, Z, ZC, ZC
    #define WF(i) ((const void*)(wf + (long)(i)*WFRAG_BYTES))

    // ---- prep: pack f pair, merged A-frag repacks, M GEMM, weight repack (M summed inside) ----
    pack8<<<(int)((long)BSZ*NC/8/256), blk>>>(f, fh, fl, (long)BSZ*NC/8);
    repack_afrag_all<<<dim3(32,3,BSZ), blk>>>(f, adj, afF, afAJ, afAJT);
    KM<<<dim3(4,4,4), blk, SM>>>(Wse1, Z, Wse2, Z, Mp, ZC,
                                 P8Z, P8Z, P8Z, nullptr, nullptr,
                                 128*CC, CC, 128*CC, CC, WSZ, CC, 128);
    repack_w<<<dim3(64,1,10), blk>>>(Wst1, Wst1b, Wst2, Wst2b, Wst3, Wst3b,
                                     Wsim1, Wsim2, Wsim3, Mp, wf);

    // ---- stage A: b3=f@Wst1, b4=f@Wst1b, b1=f@Wsim1, b2=f@M (A-frag + B-frag) ----
    KW4<<<dim3(16,2,BSZ), blk, SM>>>(
        afF, Z, WF(0), Z, b3h, b3l,
        afF, Z, WF(1), Z, b4h, b4l,
        afF, Z, WF(6), Z, b1h, b1l,
        afF, Z, WF(9), Z, b2h, b2l,
        nullptr, nullptr, NC, CC, 0, CC, NC, CC, CC);

    // ---- S = b2 @ f^T (fp32), then softmax -> pair ----
    KSG<<<dim3(2,2,BSZ), blk, SM>>>(
        b2h, b2l, fh, fl, S, ZC,
        P8Z, P8Z, P8Z, nullptr, nullptr, NC, CC, NC, CC, NNN, NN, CC);
    softmax_kernel<<<BSZ*NN, blk>>>(S, Sh, Sl);

    // ---- stage B: b5=relu(adj@b3), b2=relu(S@b1) pair, b6=relu(adjT@b4) ----
    KG3<<<dim3(12,2,BSZ), blk, SM>>>(
        afAJ, Z,  b3h, b3l, b5,  ZC,
        Sh,  Sl,  b1h, b1l, b2h, b2l,
        afAJT, Z, b4h, b4l, b6,  ZC,
        P8Z, nullptr, nullptr, NNN, NN, NC, CC, NC, CC, NN);

    // ---- stage C: b3=(b5+b6)@Wst2, b4=(b5+b6)@Wst2b, b1=b2@Wsim2 ----
    KW3<<<dim3(12,2,BSZ), blk, SM>>>(
        b5, b6, WF(2), Z, b3h, b3l,
        b5, b6, WF(3), Z, b4h, b4l,
        b2h, b2l, WF(7), Z, b1h, b1l,
        P8Z, nullptr, nullptr, NC, CC, 0, CC, NC, CC, CC);

    // ---- stage D ----
    KG3<<<dim3(12,2,BSZ), blk, SM>>>(
        afAJ, Z,  b3h, b3l, b5,  ZC,
        Sh,  Sl,  b1h, b1l, b2h, b2l,
        afAJT, Z, b4h, b4l, b6,  ZC,
        P8Z, nullptr, nullptr, NNN, NN, NC, CC, NC, CC, NN);

    // ---- stage E: b3=(b5+b6)@Wst3, b4=(b5+b6)@Wst3b, c5=b2@Wsim3 ----
    KW3<<<dim3(12,2,BSZ), blk, SM>>>(
        b5, b6, WF(4), Z, b3h, b3l,
        b5, b6, WF(5), Z, b4h, b4l,
        b2h, b2l, WF(8), Z, c5h, c5l,
        P8Z, nullptr, nullptr, NC, CC, 0, CC, NC, CC, CC);

    // ---- stage F: b5=relu(adj@b3), b6=relu(adjT@b4) ----
    KG2<<<dim3(8,2,BSZ), blk, SM>>>(
        afAJ, Z,  b3h, b3l, b5, ZC,
        afAJT, Z, b4h, b4l, b6, ZC,
        P8Z, P8Z, nullptr, nullptr, NNN, NN, NC, CC, NC, CC, NN);

    // ---- out = relu(S@c5) + b5 + b6 ----
    KFI<<<dim3(4,2,BSZ), blk, SM>>>(
        Sh, Sl, c5h, c5l, out, ZC,
        P8Z, P8Z, P8Z, b5, b6, NNN, NN, NC, CC, NC, CC, NN);
}

// round 16
// speedup vs baseline: 1.2535x; 1.0177x over previous
#include <cuda_runtime.h>
#include <cuda_bf16.h>
#include <math.h>
#include <stdint.h>

typedef __nv_bfloat16 bf16;

#define BSZ 64
#define NN  256
#define CC  512
#define NC  (NN*CC)     // 131072
#define NNN (NN*NN)     // 65536
#define WSZ (CC*CC)     // 262144
#define WFRAG_BYTES (1<<20)

// fp32 scratch
__device__ float g_b5[BSZ*NC];
__device__ float g_b6[BSZ*NC];
__device__ float g_Mp[4*WSZ];
// bf16 hi/lo pairs
__device__ __align__(256) bf16 g_b1h[BSZ*NC],  g_b1l[BSZ*NC];
__device__ __align__(256) bf16 g_b2h[BSZ*NC],  g_b2l[BSZ*NC];
__device__ __align__(256) bf16 g_b3h[BSZ*NC],  g_b3l[BSZ*NC];
__device__ __align__(256) bf16 g_b4h[BSZ*NC],  g_b4l[BSZ*NC];
__device__ __align__(256) bf16 g_c5h[BSZ*NC],  g_c5l[BSZ*NC];
__device__ __align__(256) bf16 g_Sh[BSZ*NNN],  g_Sl[BSZ*NNN];
// fragment-ordered operands
__device__ __align__(256) char g_wfrag[10*WFRAG_BYTES];  // B-frags: weights + M
__device__ __align__(256) char g_afF  [32u<<20];         // f     A-frag (K=512)
__device__ __align__(256) char g_afAJ [16u<<20];         // adj   A-frag (K=256)
__device__ __align__(256) char g_afAJT[16u<<20];         // adj^T A-frag (K=256)

#define STG        32768
#define SMEM_TOTAL (2*STG)
#define KSG_STG    40960
#define KSG_SMEM   (2*KSG_STG)

__device__ __forceinline__ uint32_t smem_u32(const void* p) {
    uint32_t a;
    asm("{ .reg .u64 t; cvta.to.shared.u64 t, %1; cvt.u32.u64 %0, t; }" : "=r"(a) : "l"(p));
    return a;
}
__device__ __forceinline__ uint32_t off_rk(uint32_t r, uint32_t cb) {
    return r * 64u + ((((cb >> 4) ^ ((r >> 1) & 3u)) & 3u) << 4) + (cb & 15u);
}
__device__ __forceinline__ uint32_t off_kn(uint32_t k, uint32_t cb) {
    uint32_t ch = (cb >> 4) ^ (k & 7u);
    return k * 256u + (ch << 4) + (cb & 15u);
}
__device__ __forceinline__ void ldsm4(uint32_t& r0, uint32_t& r1, uint32_t& r2, uint32_t& r3, uint32_t a) {
    asm volatile("ldmatrix.sync.aligned.m8n8.x4.shared.b16 {%0,%1,%2,%3}, [%4];"
                 : "=r"(r0), "=r"(r1), "=r"(r2), "=r"(r3) : "r"(a));
}
__device__ __forceinline__ void ldsm4t(uint32_t& r0, uint32_t& r1, uint32_t& r2, uint32_t& r3, uint32_t a) {
    asm volatile("ldmatrix.sync.aligned.m8n8.x4.trans.shared.b16 {%0,%1,%2,%3}, [%4];"
                 : "=r"(r0), "=r"(r1), "=r"(r2), "=r"(r3) : "r"(a));
}
__device__ __forceinline__ void mma16816(float* c, const uint32_t* a, const uint32_t* b) {
    asm volatile(
        "mma.sync.aligned.m16n8k16.row.col.f32.bf16.bf16.f32 "
        "{%0,%1,%2,%3}, {%4,%5,%6,%7}, {%8,%9}, {%0,%1,%2,%3};"
        : "+f"(c[0]), "+f"(c[1]), "+f"(c[2]), "+f"(c[3])
        : "r"(a[0]), "r"(a[1]), "r"(a[2]), "r"(a[3]), "r"(b[0]), "r"(b[1]));
}
__device__ __forceinline__ void cvt_store8(const float4 v0, const float4 v1,
                                           char* ph, char* pl) {
    float v[8] = {v0.x, v0.y, v0.z, v0.w, v1.x, v1.y, v1.z, v1.w};
    unsigned short hs[8], ls[8];
    #pragma unroll
    for (int e = 0; e < 8; e++) {
        __nv_bfloat16 hb = __float2bfloat16_rn(v[e]);
        float lf = v[e] - __bfloat162float(hb);
        __nv_bfloat16 lb = __float2bfloat16_rn(lf);
        hs[e] = *(unsigned short*)&hb;
        ls[e] = *(unsigned short*)&lb;
    }
    *(uint4*)ph = *(uint4*)hs;
    *(uint4*)pl = *(uint4*)ls;
}

// Stage one 128x32 tile into hi/lo smem.
template<int T, int P>
__device__ __forceinline__ void stage_tile(const void* __restrict__ A,
                                           const void* __restrict__ A2,
                                           int ld, int k0, int r0,
                                           char* sh, char* sl, int tid) {
    #pragma unroll
    for (int it = 0; it < 2; it++) {
        int idx = it * 256 + tid;
        int r, cb8;
        if (T == 0) { r = idx >> 2; cb8 = (idx & 3) * 8; }
        else        { r = idx >> 4; cb8 = (idx & 15) * 8; }
        long o = (T == 0) ? ((long)(r0 + r) * ld + k0 + cb8)
                          : ((long)(k0 + r) * ld + r0 + cb8);
        uint32_t off = (T == 0) ? off_rk((uint32_t)r, (uint32_t)cb8 * 2)
                                : off_kn((uint32_t)r, (uint32_t)cb8 * 2);
        if (P) {
            *(uint4*)(sh + off) = *(const uint4*)((const bf16*)A  + o);
            *(uint4*)(sl + off) = *(const uint4*)((const bf16*)A2 + o);
        } else {
            float4 a = *(const float4*)((const float*)A + o);
            float4 b = *(const float4*)((const float*)A + o + 4);
            if (A2) {
                float4 a2 = *(const float4*)((const float*)A2 + o);
                float4 b2 = *(const float4*)((const float*)A2 + o + 4);
                a.x += a2.x; a.y += a2.y; a.z += a2.z; a.w += a2.w;
                b.x += b2.x; b.y += b2.y; b.z += b2.z; b.w += b2.w;
            }
            cvt_store8(a, b, sh + off, sl + off);
        }
    }
}

// ---------------------------------------------------------------------------
// GEMM body (R15, unchanged).
// ---------------------------------------------------------------------------
template<int TA, int TB, int PA, int PB, int EPI, int OP, int BF, int AF>
__device__ __forceinline__ void gemm_body(
    const void* __restrict__ A, const void* __restrict__ A2,
    const void* __restrict__ B, const void* __restrict__ B2,
    void* __restrict__ C0, void* __restrict__ C1,
    const float* __restrict__ Add1, const float* __restrict__ Add2,
    long sA, int lda, long sB, int ldb, long sC, int ldc, int K,
    char* smem, int nx)
{
    const int tid = threadIdx.x, lane = tid & 31, wid = tid >> 5;
    const int b  = blockIdx.z;
    const int my = blockIdx.y;
    const int m0 = my * 128;
    const int n0 = nx * 128;
    const int nch = K >> 5;

    const void* Ab  = AF ? A
                         : (PA ? (const void*)((const bf16*)A  + (long)b * sA)
                               : (const void*)((const float*)A + (long)b * sA));
    const void* Ab2 = (!AF && PA) ? (const void*)((const bf16*)A2 + (long)b * sA)
                    : ((!AF && A2) ? (const void*)((const float*)A2 + (long)b * sA) : nullptr);
    const void* Bb  = BF ? B
                         : (PB ? (const void*)((const bf16*)B  + (long)b * sB)
                               : (const void*)((const float*)B + (long)b * sB));
    const void* Bb2 = (!BF && PB) ? (const void*)((const bf16*)B2 + (long)b * sB) : nullptr;

    const int am = (wid & 3) * 32;
    const int bn = (wid >> 2) * 64;
    const int bng = wid >> 2;
    const int amg = wid & 3;
    const bool USE_SMEM = (!AF) || (!BF);

    float acc[2][8][4];
    #pragma unroll
    for (int i = 0; i < 2; i++)
        #pragma unroll
        for (int j = 0; j < 8; j++)
            #pragma unroll
            for (int e = 0; e < 4; e++) acc[i][j][e] = 0.f;

    if (!AF) stage_tile<TA,PA>(Ab, Ab2, lda, 0, m0, smem, smem + 8192, tid);
    if (!BF) stage_tile<TB,PB>(Bb, Bb2, ldb, 0, n0, smem + 16384, smem + 24576, tid);
    if (USE_SMEM) __syncthreads();

    for (int ch = 0; ch < nch; ch++) {
        const int d = ch & 1;
        char* cur = smem + d * STG;
        if (ch + 1 < nch) {
            char* nxt = smem + (d ^ 1) * STG;
            if (!AF) stage_tile<TA,PA>(Ab, Ab2, lda, (ch + 1) << 5, m0, nxt, nxt + 8192, tid);
            if (!BF) stage_tile<TB,PB>(Bb, Bb2, ldb, (ch + 1) << 5, n0, nxt + 16384, nxt + 24576, tid);
        }
        const uint32_t uAh = smem_u32(cur);
        const uint32_t uAl = uAh + 8192;
        const uint32_t uBh = uAh + 16384;
        const uint32_t uBl = uAh + 24576;

        #pragma unroll
        for (int ks = 0; ks < 2; ks++) {
            uint32_t Ahf[2][4], Alf[2][4];
            if (AF) {
                const char* Af = (const char*)Ab;
                long base = ((((long)b * 2 + my) * nch + ch) * 2 + ks) * 4 + amg;
                #pragma unroll
                for (int mt = 0; mt < 2; mt++) {
                    uint4 v = *(const uint4*)(Af + ((base * 2 + mt) * 2 + 0) * 512 + lane * 16);
                    Ahf[mt][0] = v.x; Ahf[mt][1] = v.y; Ahf[mt][2] = v.z; Ahf[mt][3] = v.w;
                    uint4 u = *(const uint4*)(Af + ((base * 2 + mt) * 2 + 1) * 512 + lane * 16);
                    Alf[mt][0] = u.x; Alf[mt][1] = u.y; Alf[mt][2] = u.z; Alf[mt][3] = u.w;
                }
            } else {
                #pragma unroll
                for (int mt = 0; mt < 2; mt++) {
                    uint32_t off;
                    if (!TA) {
                        uint32_t row = (uint32_t)(am + mt * 16 + (lane & 15));
                        uint32_t cb  = (uint32_t)(ks * 32 + ((lane >> 4) << 4));
                        off = off_rk(row, cb);
                    } else {
                        uint32_t grp = lane >> 3, t8 = lane & 7;
                        uint32_t k   = (uint32_t)(ks * 16) + ((grp >> 1) << 3) + t8;
                        uint32_t cb  = (uint32_t)(am + mt * 16 + ((grp & 1) << 3)) * 2;
                        off = off_kn(k, cb);
                    }
                    if (!TA) {
                        ldsm4(Ahf[mt][0], Ahf[mt][1], Ahf[mt][2], Ahf[mt][3], uAh + off);
                        ldsm4(Alf[mt][0], Alf[mt][1], Alf[mt][2], Alf[mt][3], uAl + off);
                    } else {
                        ldsm4t(Ahf[mt][0], Ahf[mt][1], Ahf[mt][2], Ahf[mt][3], uAh + off);
                        ldsm4t(Alf[mt][0], Alf[mt][1], Alf[mt][2], Alf[mt][3], uAl + off);
                    }
                }
            }
            uint32_t Bhf[8][2], Blf[8][2];
            if (BF) {
                long blk = ((((long)nx * 16 + ch) * 2 + ks) * 2) * 2 + bng;
                const char* ph = (const char*)Bb + blk * 2048;
                const char* pl = ph + 4096;
                #pragma unroll
                for (int j = 0; j < 4; j++) {
                    uint4 v = *(const uint4*)(ph + (j * 32 + lane) * 16);
                    Bhf[2*j][0] = v.x; Bhf[2*j][1] = v.y;
                    Bhf[2*j+1][0] = v.z; Bhf[2*j+1][1] = v.w;
                }
                #pragma unroll
                for (int j = 0; j < 4; j++) {
                    uint4 v = *(const uint4*)(pl + (j * 32 + lane) * 16);
                    Blf[2*j][0] = v.x; Blf[2*j][1] = v.y;
                    Blf[2*j+1][0] = v.z; Blf[2*j+1][1] = v.w;
                }
            } else {
                #pragma unroll
                for (int p = 0; p < 4; p++) {
                    uint32_t off;
                    if (!TB) {
                        uint32_t row = (uint32_t)(bn + p * 16 + (lane & 15));
                        uint32_t cb  = (uint32_t)(ks * 32 + ((lane >> 4) << 4));
                        off = off_rk(row, cb);
                    } else {
                        uint32_t grp = lane >> 3, t8 = lane & 7;
                        uint32_t k   = (uint32_t)(ks * 16) + ((grp >> 1) << 3) + t8;
                        uint32_t cb  = (uint32_t)(bn + p * 16 + ((grp & 1) << 3)) * 2;
                        off = off_kn(k, cb);
                    }
                    uint32_t r0, r1, r2, r3;
                    if (!TB) ldsm4 (r0, r1, r2, r3, uBh + off);
                    else     ldsm4t(r0, r1, r2, r3, uBh + off);
                    Bhf[2*p][0] = r0; Bhf[2*p][1] = r2; Bhf[2*p+1][0] = r1; Bhf[2*p+1][1] = r3;
                    if (!TB) ldsm4 (r0, r1, r2, r3, uBl + off);
                    else     ldsm4t(r0, r1, r2, r3, uBl + off);
                    Blf[2*p][0] = r0; Blf[2*p][1] = r2; Blf[2*p+1][0] = r1; Blf[2*p+1][1] = r3;
                }
            }
            #pragma unroll
            for (int mt = 0; mt < 2; mt++)
                #pragma unroll
                for (int nt = 0; nt < 8; nt++) {
                    mma16816(acc[mt][nt], Ahf[mt], Bhf[nt]);
                    mma16816(acc[mt][nt], Ahf[mt], Blf[nt]);
                    mma16816(acc[mt][nt], Alf[mt], Bhf[nt]);
                }
        }
        if (USE_SMEM) __syncthreads();
    }

    #pragma unroll
    for (int mt = 0; mt < 2; mt++) {
        #pragma unroll
        for (int half = 0; half < 2; half++) {
            int row = m0 + am + mt * 16 + (lane >> 2) + half * 8;
            long base = (long)b * sC + (long)row * ldc + n0 + bn + (lane & 3) * 2;
            #pragma unroll
            for (int nt = 0; nt < 8; nt++) {
                float x = acc[mt][nt][half * 2 + 0];
                float y = acc[mt][nt][half * 2 + 1];
                if (EPI >= 1) { x = fmaxf(x, 0.f); y = fmaxf(y, 0.f); }
                if (EPI == 3) {
                    float2 o1 = *(const float2*)(Add1 + base + nt * 8);
                    float2 o2 = *(const float2*)(Add2 + base + nt * 8);
                    x += (o1.x + o2.x); y += (o1.y + o2.y);
                }
                if (OP) {
                    __nv_bfloat162 hv, lv;
                    hv.x = __float2bfloat16_rn(x);
                    lv.x = __float2bfloat16_rn(x - __bfloat162float(hv.x));
                    hv.y = __float2bfloat16_rn(y);
                    lv.y = __float2bfloat16_rn(y - __bfloat162float(hv.y));
                    *(__nv_bfloat162*)((bf16*)C0 + base + nt * 8) = hv;
                    *(__nv_bfloat162*)((bf16*)C1 + base + nt * 8) = lv;
                } else {
                    float2 v; v.x = x; v.y = y;
                    *(float2*)((float*)C0 + base + nt * 8) = v;
                }
            }
        }
    }
}

// ---------------------------------------------------------------------------
template<int PARTS,
         int TA0,int TB0,int PA0,int PB0,int EPI0,int OP0,int BF0,int AF0,
         int TA1,int TB1,int PA1,int PB1,int EPI1,int OP1,int BF1,int AF1,
         int TA2,int TB2,int PA2,int PB2,int EPI2,int OP2,int BF2,int AF2,
         int TA3,int TB3,int PA3,int PB3,int EPI3,int OP3,int BF3,int AF3>
__global__ __launch_bounds__(256)
void tc_multi(
    const void* A0, const void* A20, const void* B0, const void* B20, void* C00, void* C01,
    const void* A1, const void* A21, const void* B1, const void* B21, void* C10, void* C11,
    const void* A2, const void* A22, const void* B2, const void* B22, void* C20, void* C21,
    const void* A3, const void* A23, const void* B3, const void* B23, void* C30, void* C31,
    const float* Add1, const float* Add2,
    long sA, int lda, long sB, int ldb, long sC, int ldc, int K)
{
    extern __shared__ char smem[];
    const int p  = blockIdx.x >> 2;
    const int nx = blockIdx.x & 3;
    if (PARTS >= 4 && p == 3)
        gemm_body<TA3,TB3,PA3,PB3,EPI3,OP3,BF3,AF3>(A3, A23, B3, B23, C30, C31, Add1, Add2,
                                                    sA, lda, sB, ldb, sC, ldc, K, smem, nx);
    else if (PARTS >= 3 && p == 2)
        gemm_body<TA2,TB2,PA2,PB2,EPI2,OP2,BF2,AF2>(A2, A22, B2, B22, C20, C21, Add1, Add2,
                                                    sA, lda, sB, ldb, sC, ldc, K, smem, nx);
    else if (PARTS >= 2 && p == 1)
        gemm_body<TA1,TB1,PA1,PB1,EPI1,OP1,BF1,AF1>(A1, A21, B1, B21, C10, C11, Add1, Add2,
                                                    sA, lda, sB, ldb, sC, ldc, K, smem, nx);
    else
        gemm_body<TA0,TB0,PA0,PB0,EPI0,OP0,BF0,AF0>(A0, A20, B0, B20, C00, C01, Add1, Add2,
                                                    sA, lda, sB, ldb, sC, ldc, K, smem, nx);
}

// ---------------------------------------------------------------------------
// Fused: S-logits GEMM (b2 pair @ f^T) + row softmax -> Sh/Sl pairs.
// CTA tile M=64 x N=256 (full rows per CTA); warps 2m x 4n; K=512.
// ---------------------------------------------------------------------------
__global__ __launch_bounds__(256)
void ksg_softmax(const bf16* __restrict__ b2h_, const bf16* __restrict__ b2l_,
                 const float* __restrict__ f_,
                 bf16* __restrict__ Sh, bf16* __restrict__ Sl)
{
    extern __shared__ char smem[];
    const int tid = threadIdx.x, lane = tid & 31, wid = tid >> 5;
    const int b  = blockIdx.z;
    const int m0 = blockIdx.x * 64;
    const bf16* Ahp = b2h_ + (long)b * NC;
    const bf16* Alp = b2l_ + (long)b * NC;
    const float* fb = f_ + (long)b * NC;

    const int am = (wid & 1) * 32;
    const int bn = (wid >> 1) * 64;
    const int ng = wid >> 1;

    float acc[2][8][4];
    #pragma unroll
    for (int i = 0; i < 2; i++)
        #pragma unroll
        for (int j = 0; j < 8; j++)
            #pragma unroll
            for (int e = 0; e < 4; e++) acc[i][j][e] = 0.f;

    // stage helpers: A 64x32 pair (copy), B 256x32 fp32->pair
    auto stageA = [&](int k0, char* s) {
        int r = tid >> 2, c8 = (tid & 3) * 8;
        long o = (long)(m0 + r) * CC + k0 + c8;
        uint32_t off = off_rk((uint32_t)r, (uint32_t)c8 * 2);
        *(uint4*)(s + off)        = *(const uint4*)(Ahp + o);
        *(uint4*)(s + 4096 + off) = *(const uint4*)(Alp + o);
    };
    auto stageB = [&](int k0, char* s) {
        #pragma unroll
        for (int it = 0; it < 4; it++) {
            int idx = it * 256 + tid;
            int r = idx >> 2, c8 = (idx & 3) * 8;
            long o = (long)r * CC + k0 + c8;
            float4 a = *(const float4*)(fb + o);
            float4 bb = *(const float4*)(fb + o + 4);
            uint32_t off = off_rk((uint32_t)r, (uint32_t)c8 * 2);
            cvt_store8(a, bb, s + 8192 + off, s + 24576 + off);
        }
    };

    stageA(0, smem); stageB(0, smem);
    __syncthreads();

    const int nch = 16;
    for (int ch = 0; ch < nch; ch++) {
        const int d = ch & 1;
        char* cur = smem + d * KSG_STG;
        if (ch + 1 < nch) {
            char* nxt = smem + (d ^ 1) * KSG_STG;
            stageA((ch + 1) << 5, nxt); stageB((ch + 1) << 5, nxt);
        }
        const uint32_t uAh = smem_u32(cur);
        const uint32_t uAl = uAh + 4096;
        const uint32_t uBh = uAh + 8192;
        const uint32_t uBl = uAh + 24576;

        #pragma unroll
        for (int ks = 0; ks < 2; ks++) {
            uint32_t Ahf[2][4], Alf[2][4];
            #pragma unroll
            for (int mt = 0; mt < 2; mt++) {
                uint32_t row = (uint32_t)(am + mt * 16 + (lane & 15));
                uint32_t cb  = (uint32_t)(ks * 32 + ((lane >> 4) << 4));
                uint32_t off = off_rk(row, cb);
                ldsm4(Ahf[mt][0], Ahf[mt][1], Ahf[mt][2], Ahf[mt][3], uAh + off);
                ldsm4(Alf[mt][0], Alf[mt][1], Alf[mt][2], Alf[mt][3], uAl + off);
            }
            uint32_t Bhf[8][2], Blf[8][2];
            #pragma unroll
            for (int p = 0; p < 4; p++) {
                uint32_t row = (uint32_t)(bn + p * 16 + (lane & 15));
                uint32_t cb  = (uint32_t)(ks * 32 + ((lane >> 4) << 4));
                uint32_t off = off_rk(row, cb);
                uint32_t r0, r1, r2, r3;
                ldsm4(r0, r1, r2, r3, uBh + off);
                Bhf[2*p][0] = r0; Bhf[2*p][1] = r2; Bhf[2*p+1][0] = r1; Bhf[2*p+1][1] = r3;
                ldsm4(r0, r1, r2, r3, uBl + off);
                Blf[2*p][0] = r0; Blf[2*p][1] = r2; Blf[2*p+1][0] = r1; Blf[2*p+1][1] = r3;
            }
            #pragma unroll
            for (int mt = 0; mt < 2; mt++)
                #pragma unroll
                for (int nt = 0; nt < 8; nt++) {
                    mma16816(acc[mt][nt], Ahf[mt], Bhf[nt]);
                    mma16816(acc[mt][nt], Ahf[mt], Blf[nt]);
                    mma16816(acc[mt][nt], Alf[mt], Bhf[nt]);
                }
        }
        __syncthreads();
    }

    // ---- fused softmax over full rows (256 cols spread across 4 n-warps) ----
    float* rmax = (float*)smem;          // [4][64]
    float* rsum = (float*)(smem + 1024); // [4][64]

    // 1) row max
    #pragma unroll
    for (int mt = 0; mt < 2; mt++) {
        #pragma unroll
        for (int half = 0; half < 2; half++) {
            int r = am + mt * 16 + (lane >> 2) + half * 8;
            float mx = -3.4e38f;
            #pragma unroll
            for (int nt = 0; nt < 8; nt++) {
                mx = fmaxf(mx, acc[mt][nt][half * 2 + 0]);
                mx = fmaxf(mx, acc[mt][nt][half * 2 + 1]);
            }
            mx = fmaxf(mx, __shfl_xor_sync(0xffffffffu, mx, 1));
            mx = fmaxf(mx, __shfl_xor_sync(0xffffffffu, mx, 2));
            if ((lane & 3) == 0) rmax[ng * 64 + r] = mx;
        }
    }
    __syncthreads();
    // 2) exp + row sum
    #pragma unroll
    for (int mt = 0; mt < 2; mt++) {
        #pragma unroll
        for (int half = 0; half < 2; half++) {
            int r = am + mt * 16 + (lane >> 2) + half * 8;
            float mx = fmaxf(fmaxf(rmax[r], rmax[64 + r]),
                             fmaxf(rmax[128 + r], rmax[192 + r]));
            float s = 0.f;
            #pragma unroll
            for (int nt = 0; nt < 8; nt++) {
                float e0 = expf(acc[mt][nt][half * 2 + 0] - mx);
                float e1 = expf(acc[mt][nt][half * 2 + 1] - mx);
                acc[mt][nt][half * 2 + 0] = e0;
                acc[mt][nt][half * 2 + 1] = e1;
                s += e0 + e1;
            }
            s += __shfl_xor_sync(0xffffffffu, s, 1);
            s += __shfl_xor_sync(0xffffffffu, s, 2);
            if ((lane & 3) == 0) rsum[ng * 64 + r] = s;
        }
    }
    __syncthreads();
    // 3) normalize + pair store
    #pragma unroll
    for (int mt = 0; mt < 2; mt++) {
        #pragma unroll
        for (int half = 0; half < 2; half++) {
            int r = am + mt * 16 + (lane >> 2) + half * 8;
            float tot = rsum[r] + rsum[64 + r] + rsum[128 + r] + rsum[192 + r];
            float inv = 1.f / tot;
            long base = (long)b * NNN + (long)(m0 + r) * NN + bn + (lane & 3) * 2;
            #pragma unroll
            for (int nt = 0; nt < 8; nt++) {
                float x = acc[mt][nt][half * 2 + 0] * inv;
                float y = acc[mt][nt][half * 2 + 1] * inv;
                __nv_bfloat162 hv, lv;
                hv.x = __float2bfloat16_rn(x);
                lv.x = __float2bfloat16_rn(x - __bfloat162float(hv.x));
                hv.y = __float2bfloat16_rn(y);
                lv.y = __float2bfloat16_rn(y - __bfloat162float(hv.y));
                *(__nv_bfloat162*)(Sh + base + nt * 8) = hv;
                *(__nv_bfloat162*)(Sl + base + nt * 8) = lv;
            }
        }
    }
}

// ---------------------------------------------------------------------------
// Repack weights into B-fragment order; slot 9 sums the 4 split-K partials of M.
// ---------------------------------------------------------------------------
__global__ __launch_bounds__(256)
void repack_w(const float* s0, const float* s1, const float* s2, const float* s3,
              const float* s4, const float* s5, const float* s6, const float* s7,
              const float* s8, const float* mp, char* __restrict__ dst)
{
    __shared__ char sm[16384];
    const int z = blockIdx.z;
    const int nx = blockIdx.x >> 4, ch = blockIdx.x & 15;
    const int tid = threadIdx.x, lane = tid & 31, w = tid >> 5;

    if (z == 9) {
        #pragma unroll
        for (int it = 0; it < 2; it++) {
            int idx = it * 256 + tid;
            int kr = idx >> 4, cb8 = (idx & 15) * 8;
            long o = (long)(ch * 32 + kr) * CC + nx * 128 + cb8;
            float4 a = *(const float4*)(mp + o);
            float4 b = *(const float4*)(mp + o + 4);
            #pragma unroll
            for (int zz = 1; zz < 4; zz++) {
                float4 a2 = *(const float4*)(mp + (long)zz * WSZ + o);
                float4 b2 = *(const float4*)(mp + (long)zz * WSZ + o + 4);
                a.x += a2.x; a.y += a2.y; a.z += a2.z; a.w += a2.w;
                b.x += b2.x; b.y += b2.y; b.z += b2.z; b.w += b2.w;
            }
            uint32_t off = off_kn((uint32_t)kr, (uint32_t)cb8 * 2);
            cvt_store8(a, b, sm + off, sm + 8192 + off);
        }
    } else {
        const float* s;
        switch (z) {
            case 0: s = s0; break; case 1: s = s1; break; case 2: s = s2; break;
            case 3: s = s3; break; case 4: s = s4; break; case 5: s = s5; break;
            case 6: s = s6; break; case 7: s = s7; break; default: s = s8; break;
        }
        stage_tile<1,0>(s, nullptr, CC, ch * 32, nx * 128, sm, sm + 8192, tid);
    }
    __syncthreads();

    const int part = w & 1, bng = (w >> 1) & 1, ks = w >> 2;
    const uint32_t base = smem_u32(sm) + (uint32_t)part * 8192;
    const uint32_t grp = lane >> 3, t8 = lane & 7;
    uint32_t regs[16];
    #pragma unroll
    for (int p = 0; p < 4; p++) {
        uint32_t k  = (uint32_t)(ks * 16) + ((grp >> 1) << 3) + t8;
        uint32_t cb = (uint32_t)(bng * 64 + p * 16 + ((grp & 1) << 3)) * 2;
        uint32_t off = off_kn(k, cb);
        uint32_t r0, r1, r2, r3;
        ldsm4t(r0, r1, r2, r3, base + off);
        regs[4*p+0] = r0; regs[4*p+1] = r2; regs[4*p+2] = r1; regs[4*p+3] = r3;
    }
    long blk = ((((long)nx * 16 + ch) * 2 + ks) * 2 + part) * 2 + bng;
    char* d = dst + (long)z * WFRAG_BYTES + blk * 2048;
    #pragma unroll
    for (int j = 0; j < 4; j++)
        *(uint4*)(d + (j * 32 + lane) * 16) =
            make_uint4(regs[4*j], regs[4*j+1], regs[4*j+2], regs[4*j+3]);
}

// ---------------------------------------------------------------------------
// A-fragment repack body + merged dispatcher.
// ---------------------------------------------------------------------------
template<int T>
__device__ __forceinline__ void afrag_body(const float* __restrict__ src, long sSrc,
                                           int ld, int nch, char* __restrict__ dst,
                                           int bx)
{
    __shared__ char sm[16384];
    const int b = blockIdx.z;
    const int mtile = bx / nch;
    const int ch = bx - mtile * nch;
    const int tid = threadIdx.x, lane = tid & 31, w = tid >> 5;

    stage_tile<T,0>(src + (long)b * sSrc, nullptr, ld, ch * 32, mtile * 128,
                    sm, sm + 8192, tid);
    __syncthreads();

    const int amg = w & 3, ks = w >> 2;
    long base = ((((long)b * 2 + mtile) * nch + ch) * 2 + ks) * 4 + amg;
    #pragma unroll
    for (int mt = 0; mt < 2; mt++) {
        #pragma unroll
        for (int part = 0; part < 2; part++) {
            const uint32_t sb = smem_u32(sm) + (uint32_t)part * 8192;
            uint32_t r0, r1, r2, r3;
            if (T == 0) {
                uint32_t row = (uint32_t)(amg * 32 + mt * 16 + (lane & 15));
                uint32_t cb  = (uint32_t)(ks * 32 + ((lane >> 4) << 4));
                ldsm4(r0, r1, r2, r3, sb + off_rk(row, cb));
            } else {
                uint32_t grp = lane >> 3, t8 = lane & 7;
                uint32_t k   = (uint32_t)(ks * 16) + ((grp >> 1) << 3) + t8;
                uint32_t cb  = (uint32_t)(amg * 32 + mt * 16 + ((grp & 1) << 3)) * 2;
                ldsm4t(r0, r1, r2, r3, sb + off_kn(k, cb));
            }
            char* d = dst + ((base * 2 + mt) * 2 + part) * 512 + lane * 16;
            *(uint4*)d = make_uint4(r0, r1, r2, r3);
        }
    }
}

__global__ __launch_bounds__(256)
void repack_afrag_all(const float* __restrict__ f, const float* __restrict__ adj,
                      char* dF, char* dAJ, char* dAJT)
{
    const int which = blockIdx.y;
    if (which == 0) {
        afrag_body<0>(f, NC, CC, 16, dF, blockIdx.x);
    } else if (which == 1) {
        if (blockIdx.x >= 16) return;
        afrag_body<0>(adj, NNN, NN, 8, dAJ, blockIdx.x);
    } else {
        if (blockIdx.x >= 16) return;
        afrag_body<1>(adj, NNN, NN, 8, dAJT, blockIdx.x);
    }
}

// Instantiations
#define Z8 0,0,0,0,0,0,0,0
#define KM  tc_multi<1, 1,1,0,0,0,0,0,0, Z8, Z8, Z8>
#define KW4 tc_multi<4, 0,1,1,1,0,1,1,1, 0,1,1,1,0,1,1,1, 0,1,1,1,0,1,1,1, 0,1,1,1,0,1,1,1>
#define KG3 tc_multi<3, 0,1,1,1,1,0,0,1, 0,1,1,1,1,1,0,0, 1,1,1,1,1,0,0,1, Z8>
#define KW3 tc_multi<3, 0,1,0,1,0,1,1,0, 0,1,0,1,0,1,1,0, 0,1,1,1,0,1,1,0, Z8>
#define KG2 tc_multi<2, 0,1,1,1,1,0,0,1, 1,1,1,1,1,0,0,1, Z8, Z8>
#define KFI tc_multi<1, 0,1,1,1,3,0,0,0, Z8, Z8, Z8>

// ---------------------------------------------------------------------------
extern "C" void kernel_launch(void* const* d_in, const int* in_sizes, int n_in,
                              void* d_out, int out_size)
{
    const float* f     = (const float*)d_in[0];
    const float* adj   = (const float*)d_in[2];
    const float* Wse1  = (const float*)d_in[3];
    const float* Wse2  = (const float*)d_in[4];
    const float* Wst1  = (const float*)d_in[5];
    const float* Wst2  = (const float*)d_in[6];
    const float* Wst3  = (const float*)d_in[7];
    const float* Wst1b = (const float*)d_in[8];
    const float* Wst2b = (const float*)d_in[9];
    const float* Wst3b = (const float*)d_in[10];
    const float* Wsim1 = (const float*)d_in[11];
    const float* Wsim2 = (const float*)d_in[12];
    const float* Wsim3 = (const float*)d_in[13];
    float* out = (float*)d_out;

    float *b5, *b6, *Mp;
    bf16 *b1h, *b1l, *b2h, *b2l, *b3h, *b3l, *b4h, *b4l, *c5h, *c5l, *Sh, *Sl;
    char *wf, *afF, *afAJ, *afAJT;
    cudaGetSymbolAddress((void**)&b5, g_b5);
    cudaGetSymbolAddress((void**)&b6, g_b6);  cudaGetSymbolAddress((void**)&Mp, g_Mp);
    cudaGetSymbolAddress((void**)&b1h, g_b1h); cudaGetSymbolAddress((void**)&b1l, g_b1l);
    cudaGetSymbolAddress((void**)&b2h, g_b2h); cudaGetSymbolAddress((void**)&b2l, g_b2l);
    cudaGetSymbolAddress((void**)&b3h, g_b3h); cudaGetSymbolAddress((void**)&b3l, g_b3l);
    cudaGetSymbolAddress((void**)&b4h, g_b4h); cudaGetSymbolAddress((void**)&b4l, g_b4l);
    cudaGetSymbolAddress((void**)&c5h, g_c5h); cudaGetSymbolAddress((void**)&c5l, g_c5l);
    cudaGetSymbolAddress((void**)&Sh,  g_Sh);  cudaGetSymbolAddress((void**)&Sl,  g_Sl);
    cudaGetSymbolAddress((void**)&wf,  g_wfrag);
    cudaGetSymbolAddress((void**)&afF,  g_afF);
    cudaGetSymbolAddress((void**)&afAJ, g_afAJ);
    cudaGetSymbolAddress((void**)&afAJT,g_afAJT);

    cudaFuncSetAttribute(KM,  cudaFuncAttributeMaxDynamicSharedMemorySize, SMEM_TOTAL);
    cudaFuncSetAttribute(KW4, cudaFuncAttributeMaxDynamicSharedMemorySize, SMEM_TOTAL);
    cudaFuncSetAttribute(KG3, cudaFuncAttributeMaxDynamicSharedMemorySize, SMEM_TOTAL);
    cudaFuncSetAttribute(KW3, cudaFuncAttributeMaxDynamicSharedMemorySize, SMEM_TOTAL);
    cudaFuncSetAttribute(KG2, cudaFuncAttributeMaxDynamicSharedMemorySize, SMEM_TOTAL);
    cudaFuncSetAttribute(KFI, cudaFuncAttributeMaxDynamicSharedMemorySize, SMEM_TOTAL);
    cudaFuncSetAttribute(ksg_softmax, cudaFuncAttributeMaxDynamicSharedMemorySize, KSG_SMEM);

    const dim3 blk(256);
    const int SM = SMEM_TOTAL;
    const void* Z = nullptr;
    void* ZC = nullptr;
    #define P8Z  Z, Z, Z, Z, ZC, ZC
    #define WF(i) ((const void*)(wf + (long)(i)*WFRAG_BYTES))

    // ---- prep: merged A-frag repacks, M GEMM, weight repack (M summed inside) ----
    repack_afrag_all<<<dim3(32,3,BSZ), blk>>>(f, adj, afF, afAJ, afAJT);
    KM<<<dim3(4,4,4), blk, SM>>>(Wse1, Z, Wse2, Z, Mp, ZC,
                                 P8Z, P8Z, P8Z, nullptr, nullptr,
                                 128*CC, CC, 128*CC, CC, WSZ, CC, 128);
    repack_w<<<dim3(64,1,10), blk>>>(Wst1, Wst1b, Wst2, Wst2b, Wst3, Wst3b,
                                     Wsim1, Wsim2, Wsim3, Mp, wf);

    // ---- stage A: b3=f@Wst1, b4=f@Wst1b, b1=f@Wsim1, b2=f@M ----
    KW4<<<dim3(16,2,BSZ), blk, SM>>>(
        afF, Z, WF(0), Z, b3h, b3l,
        afF, Z, WF(1), Z, b4h, b4l,
        afF, Z, WF(6), Z, b1h, b1l,
        afF, Z, WF(9), Z, b2h, b2l,
        nullptr, nullptr, NC, CC, 0, CC, NC, CC, CC);

    // ---- fused S = softmax(b2 @ f^T) -> Sh/Sl ----
    ksg_softmax<<<dim3(4,1,BSZ), blk, KSG_SMEM>>>(b2h, b2l, f, Sh, Sl);

    // ---- stage B ----
    KG3<<<dim3(12,2,BSZ), blk, SM>>>(
        afAJ, Z,  b3h, b3l, b5,  ZC,
        Sh,  Sl,  b1h, b1l, b2h, b2l,
        afAJT, Z, b4h, b4l, b6,  ZC,
        P8Z, nullptr, nullptr, NNN, NN, NC, CC, NC, CC, NN);

    // ---- stage C ----
    KW3<<<dim3(12,2,BSZ), blk, SM>>>(
        b5, b6, WF(2), Z, b3h, b3l,
        b5, b6, WF(3), Z, b4h, b4l,
        b2h, b2l, WF(7), Z, b1h, b1l,
        P8Z, nullptr, nullptr, NC, CC, 0, CC, NC, CC, CC);

    // ---- stage D ----
    KG3<<<dim3(12,2,BSZ), blk, SM>>>(
        afAJ, Z,  b3h, b3l, b5,  ZC,
        Sh,  Sl,  b1h, b1l, b2h, b2l,
        afAJT, Z, b4h, b4l, b6,  ZC,
        P8Z, nullptr, nullptr, NNN, NN, NC, CC, NC, CC, NN);

    // ---- stage E ----
    KW3<<<dim3(12,2,BSZ), blk, SM>>>(
        b5, b6, WF(4), Z, b3h, b3l,
        b5, b6, WF(5), Z, b4h, b4l,
        b2h, b2l, WF(8), Z, c5h, c5l,
        P8Z, nullptr, nullptr, NC, CC, 0, CC, NC, CC, CC);

    // ---- stage F ----
    KG2<<<dim3(8,2,BSZ), blk, SM>>>(
        afAJ, Z,  b3h, b3l, b5, ZC,
        afAJT, Z, b4h, b4l, b6, ZC,
        P8Z, P8Z, nullptr, nullptr, NNN, NN, NC, CC, NC, CC, NN);

    // ---- out = relu(S@c5) + b5 + b6 ----
    KFI<<<dim3(4,2,BSZ), blk, SM>>>(
        Sh, Sl, c5h, c5l, out, ZC,
        P8Z, P8Z, P8Z, b5, b6, NNN, NN, NC, CC, NC, CC, NN);
}

// round 17
// speedup vs baseline: 1.3274x; 1.0589x over previous
#include <cuda_runtime.h>
#include <cuda_bf16.h>
#include <math.h>
#include <stdint.h>

typedef __nv_bfloat16 bf16;

#define BSZ 64
#define NN  256
#define CC  512
#define NC  (NN*CC)     // 131072
#define NNN (NN*NN)     // 65536
#define WSZ (CC*CC)     // 262144
#define WFRAG_BYTES (1<<20)

// fp32 scratch
__device__ float g_b5[BSZ*NC];
__device__ float g_b6[BSZ*NC];
__device__ float g_Mp[4*WSZ];
// bf16 hi/lo pairs
__device__ __align__(256) bf16 g_b1h[BSZ*NC],  g_b1l[BSZ*NC];
__device__ __align__(256) bf16 g_b2h[BSZ*NC],  g_b2l[BSZ*NC];
__device__ __align__(256) bf16 g_b3h[BSZ*NC],  g_b3l[BSZ*NC];
__device__ __align__(256) bf16 g_b4h[BSZ*NC],  g_b4l[BSZ*NC];
__device__ __align__(256) bf16 g_c5h[BSZ*NC],  g_c5l[BSZ*NC];
__device__ __align__(256) bf16 g_Sh[BSZ*NNN],  g_Sl[BSZ*NNN];
// fragment-ordered operands
__device__ __align__(256) char g_wfrag[10*WFRAG_BYTES];  // B-frags: weights + M
__device__ __align__(256) char g_afF  [32u<<20];         // f     A-frag (K=512)
__device__ __align__(256) char g_afAJ [16u<<20];         // adj   A-frag (K=256)
__device__ __align__(256) char g_afAJT[16u<<20];         // adj^T A-frag (K=256)

#define STG        32768
#define SMEM_TOTAL (2*STG)
#define KSG_STG    40960
#define KSG_SMEM   (2*KSG_STG)

__device__ __forceinline__ uint32_t smem_u32(const void* p) {
    uint32_t a;
    asm("{ .reg .u64 t; cvta.to.shared.u64 t, %1; cvt.u32.u64 %0, t; }" : "=r"(a) : "l"(p));
    return a;
}
__device__ __forceinline__ uint32_t off_rk(uint32_t r, uint32_t cb) {
    return r * 64u + ((((cb >> 4) ^ ((r >> 1) & 3u)) & 3u) << 4) + (cb & 15u);
}
__device__ __forceinline__ uint32_t off_kn(uint32_t k, uint32_t cb) {
    uint32_t ch = (cb >> 4) ^ (k & 7u);
    return k * 256u + (ch << 4) + (cb & 15u);
}
__device__ __forceinline__ void ldsm4(uint32_t& r0, uint32_t& r1, uint32_t& r2, uint32_t& r3, uint32_t a) {
    asm volatile("ldmatrix.sync.aligned.m8n8.x4.shared.b16 {%0,%1,%2,%3}, [%4];"
                 : "=r"(r0), "=r"(r1), "=r"(r2), "=r"(r3) : "r"(a));
}
__device__ __forceinline__ void ldsm4t(uint32_t& r0, uint32_t& r1, uint32_t& r2, uint32_t& r3, uint32_t a) {
    asm volatile("ldmatrix.sync.aligned.m8n8.x4.trans.shared.b16 {%0,%1,%2,%3}, [%4];"
                 : "=r"(r0), "=r"(r1), "=r"(r2), "=r"(r3) : "r"(a));
}
__device__ __forceinline__ void mma16816(float* c, const uint32_t* a, const uint32_t* b) {
    asm volatile(
        "mma.sync.aligned.m16n8k16.row.col.f32.bf16.bf16.f32 "
        "{%0,%1,%2,%3}, {%4,%5,%6,%7}, {%8,%9}, {%0,%1,%2,%3};"
        : "+f"(c[0]), "+f"(c[1]), "+f"(c[2]), "+f"(c[3])
        : "r"(a[0]), "r"(a[1]), "r"(a[2]), "r"(a[3]), "r"(b[0]), "r"(b[1]));
}
__device__ __forceinline__ void cvt_store8(const float4 v0, const float4 v1,
                                           char* ph, char* pl) {
    float v[8] = {v0.x, v0.y, v0.z, v0.w, v1.x, v1.y, v1.z, v1.w};
    unsigned short hs[8], ls[8];
    #pragma unroll
    for (int e = 0; e < 8; e++) {
        __nv_bfloat16 hb = __float2bfloat16_rn(v[e]);
        float lf = v[e] - __bfloat162float(hb);
        __nv_bfloat16 lb = __float2bfloat16_rn(lf);
        hs[e] = *(unsigned short*)&hb;
        ls[e] = *(unsigned short*)&lb;
    }
    *(uint4*)ph = *(uint4*)hs;
    *(uint4*)pl = *(uint4*)ls;
}

// Stage one 128x32 tile into hi/lo smem.
template<int T, int P>
__device__ __forceinline__ void stage_tile(const void* __restrict__ A,
                                           const void* __restrict__ A2,
                                           int ld, int k0, int r0,
                                           char* sh, char* sl, int tid) {
    #pragma unroll
    for (int it = 0; it < 2; it++) {
        int idx = it * 256 + tid;
        int r, cb8;
        if (T == 0) { r = idx >> 2; cb8 = (idx & 3) * 8; }
        else        { r = idx >> 4; cb8 = (idx & 15) * 8; }
        long o = (T == 0) ? ((long)(r0 + r) * ld + k0 + cb8)
                          : ((long)(k0 + r) * ld + r0 + cb8);
        uint32_t off = (T == 0) ? off_rk((uint32_t)r, (uint32_t)cb8 * 2)
                                : off_kn((uint32_t)r, (uint32_t)cb8 * 2);
        if (P) {
            *(uint4*)(sh + off) = *(const uint4*)((const bf16*)A  + o);
            *(uint4*)(sl + off) = *(const uint4*)((const bf16*)A2 + o);
        } else {
            float4 a = *(const float4*)((const float*)A + o);
            float4 b = *(const float4*)((const float*)A + o + 4);
            if (A2) {
                float4 a2 = *(const float4*)((const float*)A2 + o);
                float4 b2 = *(const float4*)((const float*)A2 + o + 4);
                a.x += a2.x; a.y += a2.y; a.z += a2.z; a.w += a2.w;
                b.x += b2.x; b.y += b2.y; b.z += b2.z; b.w += b2.w;
            }
            cvt_store8(a, b, sh + off, sl + off);
        }
    }
}

// ---------------------------------------------------------------------------
// GEMM body (R16, unchanged).
// ---------------------------------------------------------------------------
template<int TA, int TB, int PA, int PB, int EPI, int OP, int BF, int AF>
__device__ __forceinline__ void gemm_body(
    const void* __restrict__ A, const void* __restrict__ A2,
    const void* __restrict__ B, const void* __restrict__ B2,
    void* __restrict__ C0, void* __restrict__ C1,
    const float* __restrict__ Add1, const float* __restrict__ Add2,
    long sA, int lda, long sB, int ldb, long sC, int ldc, int K,
    char* smem, int nx)
{
    const int tid = threadIdx.x, lane = tid & 31, wid = tid >> 5;
    const int b  = blockIdx.z;
    const int my = blockIdx.y;
    const int m0 = my * 128;
    const int n0 = nx * 128;
    const int nch = K >> 5;

    const void* Ab  = AF ? A
                         : (PA ? (const void*)((const bf16*)A  + (long)b * sA)
                               : (const void*)((const float*)A + (long)b * sA));
    const void* Ab2 = (!AF && PA) ? (const void*)((const bf16*)A2 + (long)b * sA)
                    : ((!AF && A2) ? (const void*)((const float*)A2 + (long)b * sA) : nullptr);
    const void* Bb  = BF ? B
                         : (PB ? (const void*)((const bf16*)B  + (long)b * sB)
                               : (const void*)((const float*)B + (long)b * sB));
    const void* Bb2 = (!BF && PB) ? (const void*)((const bf16*)B2 + (long)b * sB) : nullptr;

    const int am = (wid & 3) * 32;
    const int bn = (wid >> 2) * 64;
    const int bng = wid >> 2;
    const int amg = wid & 3;
    const bool USE_SMEM = (!AF) || (!BF);

    float acc[2][8][4];
    #pragma unroll
    for (int i = 0; i < 2; i++)
        #pragma unroll
        for (int j = 0; j < 8; j++)
            #pragma unroll
            for (int e = 0; e < 4; e++) acc[i][j][e] = 0.f;

    if (!AF) stage_tile<TA,PA>(Ab, Ab2, lda, 0, m0, smem, smem + 8192, tid);
    if (!BF) stage_tile<TB,PB>(Bb, Bb2, ldb, 0, n0, smem + 16384, smem + 24576, tid);
    if (USE_SMEM) __syncthreads();

    for (int ch = 0; ch < nch; ch++) {
        const int d = ch & 1;
        char* cur = smem + d * STG;
        if (ch + 1 < nch) {
            char* nxt = smem + (d ^ 1) * STG;
            if (!AF) stage_tile<TA,PA>(Ab, Ab2, lda, (ch + 1) << 5, m0, nxt, nxt + 8192, tid);
            if (!BF) stage_tile<TB,PB>(Bb, Bb2, ldb, (ch + 1) << 5, n0, nxt + 16384, nxt + 24576, tid);
        }
        const uint32_t uAh = smem_u32(cur);
        const uint32_t uAl = uAh + 8192;
        const uint32_t uBh = uAh + 16384;
        const uint32_t uBl = uAh + 24576;

        #pragma unroll
        for (int ks = 0; ks < 2; ks++) {
            uint32_t Ahf[2][4], Alf[2][4];
            if (AF) {
                const char* Af = (const char*)Ab;
                long base = ((((long)b * 2 + my) * nch + ch) * 2 + ks) * 4 + amg;
                #pragma unroll
                for (int mt = 0; mt < 2; mt++) {
                    uint4 v = *(const uint4*)(Af + ((base * 2 + mt) * 2 + 0) * 512 + lane * 16);
                    Ahf[mt][0] = v.x; Ahf[mt][1] = v.y; Ahf[mt][2] = v.z; Ahf[mt][3] = v.w;
                    uint4 u = *(const uint4*)(Af + ((base * 2 + mt) * 2 + 1) * 512 + lane * 16);
                    Alf[mt][0] = u.x; Alf[mt][1] = u.y; Alf[mt][2] = u.z; Alf[mt][3] = u.w;
                }
            } else {
                #pragma unroll
                for (int mt = 0; mt < 2; mt++) {
                    uint32_t off;
                    if (!TA) {
                        uint32_t row = (uint32_t)(am + mt * 16 + (lane & 15));
                        uint32_t cb  = (uint32_t)(ks * 32 + ((lane >> 4) << 4));
                        off = off_rk(row, cb);
                    } else {
                        uint32_t grp = lane >> 3, t8 = lane & 7;
                        uint32_t k   = (uint32_t)(ks * 16) + ((grp >> 1) << 3) + t8;
                        uint32_t cb  = (uint32_t)(am + mt * 16 + ((grp & 1) << 3)) * 2;
                        off = off_kn(k, cb);
                    }
                    if (!TA) {
                        ldsm4(Ahf[mt][0], Ahf[mt][1], Ahf[mt][2], Ahf[mt][3], uAh + off);
                        ldsm4(Alf[mt][0], Alf[mt][1], Alf[mt][2], Alf[mt][3], uAl + off);
                    } else {
                        ldsm4t(Ahf[mt][0], Ahf[mt][1], Ahf[mt][2], Ahf[mt][3], uAh + off);
                        ldsm4t(Alf[mt][0], Alf[mt][1], Alf[mt][2], Alf[mt][3], uAl + off);
                    }
                }
            }
            uint32_t Bhf[8][2], Blf[8][2];
            if (BF) {
                long blk = ((((long)nx * 16 + ch) * 2 + ks) * 2) * 2 + bng;
                const char* ph = (const char*)Bb + blk * 2048;
                const char* pl = ph + 4096;
                #pragma unroll
                for (int j = 0; j < 4; j++) {
                    uint4 v = *(const uint4*)(ph + (j * 32 + lane) * 16);
                    Bhf[2*j][0] = v.x; Bhf[2*j][1] = v.y;
                    Bhf[2*j+1][0] = v.z; Bhf[2*j+1][1] = v.w;
                }
                #pragma unroll
                for (int j = 0; j < 4; j++) {
                    uint4 v = *(const uint4*)(pl + (j * 32 + lane) * 16);
                    Blf[2*j][0] = v.x; Blf[2*j][1] = v.y;
                    Blf[2*j+1][0] = v.z; Blf[2*j+1][1] = v.w;
                }
            } else {
                #pragma unroll
                for (int p = 0; p < 4; p++) {
                    uint32_t off;
                    if (!TB) {
                        uint32_t row = (uint32_t)(bn + p * 16 + (lane & 15));
                        uint32_t cb  = (uint32_t)(ks * 32 + ((lane >> 4) << 4));
                        off = off_rk(row, cb);
                    } else {
                        uint32_t grp = lane >> 3, t8 = lane & 7;
                        uint32_t k   = (uint32_t)(ks * 16) + ((grp >> 1) << 3) + t8;
                        uint32_t cb  = (uint32_t)(bn + p * 16 + ((grp & 1) << 3)) * 2;
                        off = off_kn(k, cb);
                    }
                    uint32_t r0, r1, r2, r3;
                    if (!TB) ldsm4 (r0, r1, r2, r3, uBh + off);
                    else     ldsm4t(r0, r1, r2, r3, uBh + off);
                    Bhf[2*p][0] = r0; Bhf[2*p][1] = r2; Bhf[2*p+1][0] = r1; Bhf[2*p+1][1] = r3;
                    if (!TB) ldsm4 (r0, r1, r2, r3, uBl + off);
                    else     ldsm4t(r0, r1, r2, r3, uBl + off);
                    Blf[2*p][0] = r0; Blf[2*p][1] = r2; Blf[2*p+1][0] = r1; Blf[2*p+1][1] = r3;
                }
            }
            #pragma unroll
            for (int mt = 0; mt < 2; mt++)
                #pragma unroll
                for (int nt = 0; nt < 8; nt++) {
                    mma16816(acc[mt][nt], Ahf[mt], Bhf[nt]);
                    mma16816(acc[mt][nt], Ahf[mt], Blf[nt]);
                    mma16816(acc[mt][nt], Alf[mt], Bhf[nt]);
                }
        }
        if (USE_SMEM) __syncthreads();
    }

    #pragma unroll
    for (int mt = 0; mt < 2; mt++) {
        #pragma unroll
        for (int half = 0; half < 2; half++) {
            int row = m0 + am + mt * 16 + (lane >> 2) + half * 8;
            long base = (long)b * sC + (long)row * ldc + n0 + bn + (lane & 3) * 2;
            #pragma unroll
            for (int nt = 0; nt < 8; nt++) {
                float x = acc[mt][nt][half * 2 + 0];
                float y = acc[mt][nt][half * 2 + 1];
                if (EPI >= 1) { x = fmaxf(x, 0.f); y = fmaxf(y, 0.f); }
                if (EPI == 3) {
                    float2 o1 = *(const float2*)(Add1 + base + nt * 8);
                    float2 o2 = *(const float2*)(Add2 + base + nt * 8);
                    x += (o1.x + o2.x); y += (o1.y + o2.y);
                }
                if (OP) {
                    __nv_bfloat162 hv, lv;
                    hv.x = __float2bfloat16_rn(x);
                    lv.x = __float2bfloat16_rn(x - __bfloat162float(hv.x));
                    hv.y = __float2bfloat16_rn(y);
                    lv.y = __float2bfloat16_rn(y - __bfloat162float(hv.y));
                    *(__nv_bfloat162*)((bf16*)C0 + base + nt * 8) = hv;
                    *(__nv_bfloat162*)((bf16*)C1 + base + nt * 8) = lv;
                } else {
                    float2 v; v.x = x; v.y = y;
                    *(float2*)((float*)C0 + base + nt * 8) = v;
                }
            }
        }
    }
}

// ---------------------------------------------------------------------------
// NOTE: __launch_bounds__(256, 2) — cap regs at 128 so 2 CTAs/SM always fit.
// ---------------------------------------------------------------------------
template<int PARTS,
         int TA0,int TB0,int PA0,int PB0,int EPI0,int OP0,int BF0,int AF0,
         int TA1,int TB1,int PA1,int PB1,int EPI1,int OP1,int BF1,int AF1,
         int TA2,int TB2,int PA2,int PB2,int EPI2,int OP2,int BF2,int AF2,
         int TA3,int TB3,int PA3,int PB3,int EPI3,int OP3,int BF3,int AF3>
__global__ __launch_bounds__(256, 2)
void tc_multi(
    const void* A0, const void* A20, const void* B0, const void* B20, void* C00, void* C01,
    const void* A1, const void* A21, const void* B1, const void* B21, void* C10, void* C11,
    const void* A2, const void* A22, const void* B2, const void* B22, void* C20, void* C21,
    const void* A3, const void* A23, const void* B3, const void* B23, void* C30, void* C31,
    const float* Add1, const float* Add2,
    long sA, int lda, long sB, int ldb, long sC, int ldc, int K)
{
    extern __shared__ char smem[];
    const int p  = blockIdx.x >> 2;
    const int nx = blockIdx.x & 3;
    if (PARTS >= 4 && p == 3)
        gemm_body<TA3,TB3,PA3,PB3,EPI3,OP3,BF3,AF3>(A3, A23, B3, B23, C30, C31, Add1, Add2,
                                                    sA, lda, sB, ldb, sC, ldc, K, smem, nx);
    else if (PARTS >= 3 && p == 2)
        gemm_body<TA2,TB2,PA2,PB2,EPI2,OP2,BF2,AF2>(A2, A22, B2, B22, C20, C21, Add1, Add2,
                                                    sA, lda, sB, ldb, sC, ldc, K, smem, nx);
    else if (PARTS >= 2 && p == 1)
        gemm_body<TA1,TB1,PA1,PB1,EPI1,OP1,BF1,AF1>(A1, A21, B1, B21, C10, C11, Add1, Add2,
                                                    sA, lda, sB, ldb, sC, ldc, K, smem, nx);
    else
        gemm_body<TA0,TB0,PA0,PB0,EPI0,OP0,BF0,AF0>(A0, A20, B0, B20, C00, C01, Add1, Add2,
                                                    sA, lda, sB, ldb, sC, ldc, K, smem, nx);
}

// ---------------------------------------------------------------------------
// Fused: S-logits GEMM (b2 pair @ f^T) + row softmax -> Sh/Sl pairs.
// ---------------------------------------------------------------------------
__global__ __launch_bounds__(256, 2)
void ksg_softmax(const bf16* __restrict__ b2h_, const bf16* __restrict__ b2l_,
                 const float* __restrict__ f_,
                 bf16* __restrict__ Sh, bf16* __restrict__ Sl)
{
    extern __shared__ char smem[];
    const int tid = threadIdx.x, lane = tid & 31, wid = tid >> 5;
    const int b  = blockIdx.z;
    const int m0 = blockIdx.x * 64;
    const bf16* Ahp = b2h_ + (long)b * NC;
    const bf16* Alp = b2l_ + (long)b * NC;
    const float* fb = f_ + (long)b * NC;

    const int am = (wid & 1) * 32;
    const int bn = (wid >> 1) * 64;
    const int ng = wid >> 1;

    float acc[2][8][4];
    #pragma unroll
    for (int i = 0; i < 2; i++)
        #pragma unroll
        for (int j = 0; j < 8; j++)
            #pragma unroll
            for (int e = 0; e < 4; e++) acc[i][j][e] = 0.f;

    auto stageA = [&](int k0, char* s) {
        int r = tid >> 2, c8 = (tid & 3) * 8;
        long o = (long)(m0 + r) * CC + k0 + c8;
        uint32_t off = off_rk((uint32_t)r, (uint32_t)c8 * 2);
        *(uint4*)(s + off)        = *(const uint4*)(Ahp + o);
        *(uint4*)(s + 4096 + off) = *(const uint4*)(Alp + o);
    };
    auto stageB = [&](int k0, char* s) {
        #pragma unroll
        for (int it = 0; it < 4; it++) {
            int idx = it * 256 + tid;
            int r = idx >> 2, c8 = (idx & 3) * 8;
            long o = (long)r * CC + k0 + c8;
            float4 a = *(const float4*)(fb + o);
            float4 bb = *(const float4*)(fb + o + 4);
            uint32_t off = off_rk((uint32_t)r, (uint32_t)c8 * 2);
            cvt_store8(a, bb, s + 8192 + off, s + 24576 + off);
        }
    };

    stageA(0, smem); stageB(0, smem);
    __syncthreads();

    const int nch = 16;
    for (int ch = 0; ch < nch; ch++) {
        const int d = ch & 1;
        char* cur = smem + d * KSG_STG;
        if (ch + 1 < nch) {
            char* nxt = smem + (d ^ 1) * KSG_STG;
            stageA((ch + 1) << 5, nxt); stageB((ch + 1) << 5, nxt);
        }
        const uint32_t uAh = smem_u32(cur);
        const uint32_t uAl = uAh + 4096;
        const uint32_t uBh = uAh + 8192;
        const uint32_t uBl = uAh + 24576;

        #pragma unroll
        for (int ks = 0; ks < 2; ks++) {
            uint32_t Ahf[2][4], Alf[2][4];
            #pragma unroll
            for (int mt = 0; mt < 2; mt++) {
                uint32_t row = (uint32_t)(am + mt * 16 + (lane & 15));
                uint32_t cb  = (uint32_t)(ks * 32 + ((lane >> 4) << 4));
                uint32_t off = off_rk(row, cb);
                ldsm4(Ahf[mt][0], Ahf[mt][1], Ahf[mt][2], Ahf[mt][3], uAh + off);
                ldsm4(Alf[mt][0], Alf[mt][1], Alf[mt][2], Alf[mt][3], uAl + off);
            }
            uint32_t Bhf[8][2], Blf[8][2];
            #pragma unroll
            for (int p = 0; p < 4; p++) {
                uint32_t row = (uint32_t)(bn + p * 16 + (lane & 15));
                uint32_t cb  = (uint32_t)(ks * 32 + ((lane >> 4) << 4));
                uint32_t off = off_rk(row, cb);
                uint32_t r0, r1, r2, r3;
                ldsm4(r0, r1, r2, r3, uBh + off);
                Bhf[2*p][0] = r0; Bhf[2*p][1] = r2; Bhf[2*p+1][0] = r1; Bhf[2*p+1][1] = r3;
                ldsm4(r0, r1, r2, r3, uBl + off);
                Blf[2*p][0] = r0; Blf[2*p][1] = r2; Blf[2*p+1][0] = r1; Blf[2*p+1][1] = r3;
            }
            #pragma unroll
            for (int mt = 0; mt < 2; mt++)
                #pragma unroll
                for (int nt = 0; nt < 8; nt++) {
                    mma16816(acc[mt][nt], Ahf[mt], Bhf[nt]);
                    mma16816(acc[mt][nt], Ahf[mt], Blf[nt]);
                    mma16816(acc[mt][nt], Alf[mt], Bhf[nt]);
                }
        }
        __syncthreads();
    }

    float* rmax = (float*)smem;
    float* rsum = (float*)(smem + 1024);

    #pragma unroll
    for (int mt = 0; mt < 2; mt++) {
        #pragma unroll
        for (int half = 0; half < 2; half++) {
            int r = am + mt * 16 + (lane >> 2) + half * 8;
            float mx = -3.4e38f;
            #pragma unroll
            for (int nt = 0; nt < 8; nt++) {
                mx = fmaxf(mx, acc[mt][nt][half * 2 + 0]);
                mx = fmaxf(mx, acc[mt][nt][half * 2 + 1]);
            }
            mx = fmaxf(mx, __shfl_xor_sync(0xffffffffu, mx, 1));
            mx = fmaxf(mx, __shfl_xor_sync(0xffffffffu, mx, 2));
            if ((lane & 3) == 0) rmax[ng * 64 + r] = mx;
        }
    }
    __syncthreads();
    #pragma unroll
    for (int mt = 0; mt < 2; mt++) {
        #pragma unroll
        for (int half = 0; half < 2; half++) {
            int r = am + mt * 16 + (lane >> 2) + half * 8;
            float mx = fmaxf(fmaxf(rmax[r], rmax[64 + r]),
                             fmaxf(rmax[128 + r], rmax[192 + r]));
            float s = 0.f;
            #pragma unroll
            for (int nt = 0; nt < 8; nt++) {
                float e0 = expf(acc[mt][nt][half * 2 + 0] - mx);
                float e1 = expf(acc[mt][nt][half * 2 + 1] - mx);
                acc[mt][nt][half * 2 + 0] = e0;
                acc[mt][nt][half * 2 + 1] = e1;
                s += e0 + e1;
            }
            s += __shfl_xor_sync(0xffffffffu, s, 1);
            s += __shfl_xor_sync(0xffffffffu, s, 2);
            if ((lane & 3) == 0) rsum[ng * 64 + r] = s;
        }
    }
    __syncthreads();
    #pragma unroll
    for (int mt = 0; mt < 2; mt++) {
        #pragma unroll
        for (int half = 0; half < 2; half++) {
            int r = am + mt * 16 + (lane >> 2) + half * 8;
            float tot = rsum[r] + rsum[64 + r] + rsum[128 + r] + rsum[192 + r];
            float inv = 1.f / tot;
            long base = (long)b * NNN + (long)(m0 + r) * NN + bn + (lane & 3) * 2;
            #pragma unroll
            for (int nt = 0; nt < 8; nt++) {
                float x = acc[mt][nt][half * 2 + 0] * inv;
                float y = acc[mt][nt][half * 2 + 1] * inv;
                __nv_bfloat162 hv, lv;
                hv.x = __float2bfloat16_rn(x);
                lv.x = __float2bfloat16_rn(x - __bfloat162float(hv.x));
                hv.y = __float2bfloat16_rn(y);
                lv.y = __float2bfloat16_rn(y - __bfloat162float(hv.y));
                *(__nv_bfloat162*)(Sh + base + nt * 8) = hv;
                *(__nv_bfloat162*)(Sl + base + nt * 8) = lv;
            }
        }
    }
}

// ---------------------------------------------------------------------------
__global__ __launch_bounds__(256)
void repack_w(const float* s0, const float* s1, const float* s2, const float* s3,
              const float* s4, const float* s5, const float* s6, const float* s7,
              const float* s8, const float* mp, char* __restrict__ dst)
{
    __shared__ char sm[16384];
    const int z = blockIdx.z;
    const int nx = blockIdx.x >> 4, ch = blockIdx.x & 15;
    const int tid = threadIdx.x, lane = tid & 31, w = tid >> 5;

    if (z == 9) {
        #pragma unroll
        for (int it = 0; it < 2; it++) {
            int idx = it * 256 + tid;
            int kr = idx >> 4, cb8 = (idx & 15) * 8;
            long o = (long)(ch * 32 + kr) * CC + nx * 128 + cb8;
            float4 a = *(const float4*)(mp + o);
            float4 b = *(const float4*)(mp + o + 4);
            #pragma unroll
            for (int zz = 1; zz < 4; zz++) {
                float4 a2 = *(const float4*)(mp + (long)zz * WSZ + o);
                float4 b2 = *(const float4*)(mp + (long)zz * WSZ + o + 4);
                a.x += a2.x; a.y += a2.y; a.z += a2.z; a.w += a2.w;
                b.x += b2.x; b.y += b2.y; b.z += b2.z; b.w += b2.w;
            }
            uint32_t off = off_kn((uint32_t)kr, (uint32_t)cb8 * 2);
            cvt_store8(a, b, sm + off, sm + 8192 + off);
        }
    } else {
        const float* s;
        switch (z) {
            case 0: s = s0; break; case 1: s = s1; break; case 2: s = s2; break;
            case 3: s = s3; break; case 4: s = s4; break; case 5: s = s5; break;
            case 6: s = s6; break; case 7: s = s7; break; default: s = s8; break;
        }
        stage_tile<1,0>(s, nullptr, CC, ch * 32, nx * 128, sm, sm + 8192, tid);
    }
    __syncthreads();

    const int part = w & 1, bng = (w >> 1) & 1, ks = w >> 2;
    const uint32_t base = smem_u32(sm) + (uint32_t)part * 8192;
    const uint32_t grp = lane >> 3, t8 = lane & 7;
    uint32_t regs[16];
    #pragma unroll
    for (int p = 0; p < 4; p++) {
        uint32_t k  = (uint32_t)(ks * 16) + ((grp >> 1) << 3) + t8;
        uint32_t cb = (uint32_t)(bng * 64 + p * 16 + ((grp & 1) << 3)) * 2;
        uint32_t off = off_kn(k, cb);
        uint32_t r0, r1, r2, r3;
        ldsm4t(r0, r1, r2, r3, base + off);
        regs[4*p+0] = r0; regs[4*p+1] = r2; regs[4*p+2] = r1; regs[4*p+3] = r3;
    }
    long blk = ((((long)nx * 16 + ch) * 2 + ks) * 2 + part) * 2 + bng;
    char* d = dst + (long)z * WFRAG_BYTES + blk * 2048;
    #pragma unroll
    for (int j = 0; j < 4; j++)
        *(uint4*)(d + (j * 32 + lane) * 16) =
            make_uint4(regs[4*j], regs[4*j+1], regs[4*j+2], regs[4*j+3]);
}

// ---------------------------------------------------------------------------
template<int T>
__device__ __forceinline__ void afrag_body(const float* __restrict__ src, long sSrc,
                                           int ld, int nch, char* __restrict__ dst,
                                           int bx)
{
    __shared__ char sm[16384];
    const int b = blockIdx.z;
    const int mtile = bx / nch;
    const int ch = bx - mtile * nch;
    const int tid = threadIdx.x, lane = tid & 31, w = tid >> 5;

    stage_tile<T,0>(src + (long)b * sSrc, nullptr, ld, ch * 32, mtile * 128,
                    sm, sm + 8192, tid);
    __syncthreads();

    const int amg = w & 3, ks = w >> 2;
    long base = ((((long)b * 2 + mtile) * nch + ch) * 2 + ks) * 4 + amg;
    #pragma unroll
    for (int mt = 0; mt < 2; mt++) {
        #pragma unroll
        for (int part = 0; part < 2; part++) {
            const uint32_t sb = smem_u32(sm) + (uint32_t)part * 8192;
            uint32_t r0, r1, r2, r3;
            if (T == 0) {
                uint32_t row = (uint32_t)(amg * 32 + mt * 16 + (lane & 15));
                uint32_t cb  = (uint32_t)(ks * 32 + ((lane >> 4) << 4));
                ldsm4(r0, r1, r2, r3, sb + off_rk(row, cb));
            } else {
                uint32_t grp = lane >> 3, t8 = lane & 7;
                uint32_t k   = (uint32_t)(ks * 16) + ((grp >> 1) << 3) + t8;
                uint32_t cb  = (uint32_t)(amg * 32 + mt * 16 + ((grp & 1) << 3)) * 2;
                ldsm4t(r0, r1, r2, r3, sb + off_kn(k, cb));
            }
            char* d = dst + ((base * 2 + mt) * 2 + part) * 512 + lane * 16;
            *(uint4*)d = make_uint4(r0, r1, r2, r3);
        }
    }
}

__global__ __launch_bounds__(256)
void repack_afrag_all(const float* __restrict__ f, const float* __restrict__ adj,
                      char* dF, char* dAJ, char* dAJT)
{
    const int which = blockIdx.y;
    if (which == 0) {
        afrag_body<0>(f, NC, CC, 16, dF, blockIdx.x);
    } else if (which == 1) {
        if (blockIdx.x >= 16) return;
        afrag_body<0>(adj, NNN, NN, 8, dAJ, blockIdx.x);
    } else {
        if (blockIdx.x >= 16) return;
        afrag_body<1>(adj, NNN, NN, 8, dAJT, blockIdx.x);
    }
}

// Instantiations
#define Z8 0,0,0,0,0,0,0,0
#define KM  tc_multi<1, 1,1,0,0,0,0,0,0, Z8, Z8, Z8>
#define KW4 tc_multi<4, 0,1,1,1,0,1,1,1, 0,1,1,1,0,1,1,1, 0,1,1,1,0,1,1,1, 0,1,1,1,0,1,1,1>
#define KG3 tc_multi<3, 0,1,1,1,1,0,0,1, 0,1,1,1,1,1,0,0, 1,1,1,1,1,0,0,1, Z8>
#define KW3 tc_multi<3, 0,1,0,1,0,1,1,0, 0,1,0,1,0,1,1,0, 0,1,1,1,0,1,1,0, Z8>
#define KG2 tc_multi<2, 0,1,1,1,1,0,0,1, 1,1,1,1,1,0,0,1, Z8, Z8>
#define KFI tc_multi<1, 0,1,1,1,3,0,0,0, Z8, Z8, Z8>

// ---------------------------------------------------------------------------
extern "C" void kernel_launch(void* const* d_in, const int* in_sizes, int n_in,
                              void* d_out, int out_size)
{
    const float* f     = (const float*)d_in[0];
    const float* adj   = (const float*)d_in[2];
    const float* Wse1  = (const float*)d_in[3];
    const float* Wse2  = (const float*)d_in[4];
    const float* Wst1  = (const float*)d_in[5];
    const float* Wst2  = (const float*)d_in[6];
    const float* Wst3  = (const float*)d_in[7];
    const float* Wst1b = (const float*)d_in[8];
    const float* Wst2b = (const float*)d_in[9];
    const float* Wst3b = (const float*)d_in[10];
    const float* Wsim1 = (const float*)d_in[11];
    const float* Wsim2 = (const float*)d_in[12];
    const float* Wsim3 = (const float*)d_in[13];
    float* out = (float*)d_out;

    float *b5, *b6, *Mp;
    bf16 *b1h, *b1l, *b2h, *b2l, *b3h, *b3l, *b4h, *b4l, *c5h, *c5l, *Sh, *Sl;
    char *wf, *afF, *afAJ, *afAJT;
    cudaGetSymbolAddress((void**)&b5, g_b5);
    cudaGetSymbolAddress((void**)&b6, g_b6);  cudaGetSymbolAddress((void**)&Mp, g_Mp);
    cudaGetSymbolAddress((void**)&b1h, g_b1h); cudaGetSymbolAddress((void**)&b1l, g_b1l);
    cudaGetSymbolAddress((void**)&b2h, g_b2h); cudaGetSymbolAddress((void**)&b2l, g_b2l);
    cudaGetSymbolAddress((void**)&b3h, g_b3h); cudaGetSymbolAddress((void**)&b3l, g_b3l);
    cudaGetSymbolAddress((void**)&b4h, g_b4h); cudaGetSymbolAddress((void**)&b4l, g_b4l);
    cudaGetSymbolAddress((void**)&c5h, g_c5h); cudaGetSymbolAddress((void**)&c5l, g_c5l);
    cudaGetSymbolAddress((void**)&Sh,  g_Sh);  cudaGetSymbolAddress((void**)&Sl,  g_Sl);
    cudaGetSymbolAddress((void**)&wf,  g_wfrag);
    cudaGetSymbolAddress((void**)&afF,  g_afF);
    cudaGetSymbolAddress((void**)&afAJ, g_afAJ);
    cudaGetSymbolAddress((void**)&afAJT,g_afAJT);

    cudaFuncSetAttribute(KM,  cudaFuncAttributeMaxDynamicSharedMemorySize, SMEM_TOTAL);
    cudaFuncSetAttribute(KW4, cudaFuncAttributeMaxDynamicSharedMemorySize, SMEM_TOTAL);
    cudaFuncSetAttribute(KG3, cudaFuncAttributeMaxDynamicSharedMemorySize, SMEM_TOTAL);
    cudaFuncSetAttribute(KW3, cudaFuncAttributeMaxDynamicSharedMemorySize, SMEM_TOTAL);
    cudaFuncSetAttribute(KG2, cudaFuncAttributeMaxDynamicSharedMemorySize, SMEM_TOTAL);
    cudaFuncSetAttribute(KFI, cudaFuncAttributeMaxDynamicSharedMemorySize, SMEM_TOTAL);
    cudaFuncSetAttribute(ksg_softmax, cudaFuncAttributeMaxDynamicSharedMemorySize, KSG_SMEM);

    const dim3 blk(256);
    const int SM = SMEM_TOTAL;
    const void* Z = nullptr;
    void* ZC = nullptr;
    #define P8Z  Z, Z, Z, Z, ZC, ZC
    #define WF(i) ((const void*)(wf + (long)(i)*WFRAG_BYTES))

    // ---- prep ----
    repack_afrag_all<<<dim3(32,3,BSZ), blk>>>(f, adj, afF, afAJ, afAJT);
    KM<<<dim3(4,4,4), blk, SM>>>(Wse1, Z, Wse2, Z, Mp, ZC,
                                 P8Z, P8Z, P8Z, nullptr, nullptr,
                                 128*CC, CC, 128*CC, CC, WSZ, CC, 128);
    repack_w<<<dim3(64,1,10), blk>>>(Wst1, Wst1b, Wst2, Wst2b, Wst3, Wst3b,
                                     Wsim1, Wsim2, Wsim3, Mp, wf);

    // ---- stage A ----
    KW4<<<dim3(16,2,BSZ), blk, SM>>>(
        afF, Z, WF(0), Z, b3h, b3l,
        afF, Z, WF(1), Z, b4h, b4l,
        afF, Z, WF(6), Z, b1h, b1l,
        afF, Z, WF(9), Z, b2h, b2l,
        nullptr, nullptr, NC, CC, 0, CC, NC, CC, CC);

    // ---- fused S = softmax(b2 @ f^T) ----
    ksg_softmax<<<dim3(4,1,BSZ), blk, KSG_SMEM>>>(b2h, b2l, f, Sh, Sl);

    // ---- stage B ----
    KG3<<<dim3(12,2,BSZ), blk, SM>>>(
        afAJ, Z,  b3h, b3l, b5,  ZC,
        Sh,  Sl,  b1h, b1l, b2h, b2l,
        afAJT, Z, b4h, b4l, b6,  ZC,
        P8Z, nullptr, nullptr, NNN, NN, NC, CC, NC, CC, NN);

    // ---- stage C ----
    KW3<<<dim3(12,2,BSZ), blk, SM>>>(
        b5, b6, WF(2), Z, b3h, b3l,
        b5, b6, WF(3), Z, b4h, b4l,
        b2h, b2l, WF(7), Z, b1h, b1l,
        P8Z, nullptr, nullptr, NC, CC, 0, CC, NC, CC, CC);

    // ---- stage D ----
    KG3<<<dim3(12,2,BSZ), blk, SM>>>(
        afAJ, Z,  b3h, b3l, b5,  ZC,
        Sh,  Sl,  b1h, b1l, b2h, b2l,
        afAJT, Z, b4h, b4l, b6,  ZC,
        P8Z, nullptr, nullptr, NNN, NN, NC, CC, NC, CC, NN);

    // ---- stage E ----
    KW3<<<dim3(12,2,BSZ), blk, SM>>>(
        b5, b6, WF(4), Z, b3h, b3l,
        b5, b6, WF(5), Z, b4h, b4l,
        b2h, b2l, WF(8), Z, c5h, c5l,
        P8Z, nullptr, nullptr, NC, CC, 0, CC, NC, CC, CC);

    // ---- stage F ----
    KG2<<<dim3(8,2,BSZ), blk, SM>>>(
        afAJ, Z,  b3h, b3l, b5, ZC,
        afAJT, Z, b4h, b4l, b6, ZC,
        P8Z, P8Z, nullptr, nullptr, NNN, NN, NC, CC, NC, CC, NN);

    // ---- out = relu(S@c5) + b5 + b6 ----
    KFI<<<dim3(4,2,BSZ), blk, SM>>>(
        Sh, Sl, c5h, c5l, out, ZC,
        P8Z, P8Z, P8Z, b5, b6, NNN, NN, NC, CC, NC, CC, NN);
}